// round 10
// baseline (speedup 1.0000x reference)
#include <cuda_runtime.h>
#include <cuda_bf16.h>
#include <math.h>

#define BATCH 4
#define SLEN  2048
#define HID   896
#define NH    14
#define NKV   2
#define HD    64
#define NREP  (NH / NKV)

typedef unsigned long long u64;
typedef unsigned int u32;
typedef unsigned short u16;

#define NA (8192 * 896)
#define NW (2048 * 896)
#define NQE (BATCH * NH * SLEN * HD)
#define NKE (BATCH * NKV * SLEN * HD)

// ---------------- scratch ----------------
__device__ float g_Q[NQE];
__device__ float g_K[NKE];
__device__ u16 g_Ah[NA], g_Al[NA];
__device__ u16 g_Wh[NW], g_Wl[NW];
__device__ u16 g_Qh[NQE], g_Ql[NQE];
__device__ u16 g_Kh[NKE], g_Kl[NKE];
__device__ u16 g_Vh[NKE], g_Vl[NKE];
__device__ u16 g_Oh[NA], g_Ol[NA];
__device__ float g_invf[HD / 2];

__global__ void init_invf_kernel() {
    int i = threadIdx.x;
    if (i < HD / 2) g_invf[i] = (float)pow(1.0e6, -(double)i / 32.0);
}

// ================= helpers =================
__device__ __forceinline__ u32 smem_u32(const void* p) {
    u32 a;
    asm("{ .reg .u64 t; cvta.to.shared.u64 t, %1; cvt.u32.u64 %0, t; }" : "=r"(a) : "l"(p));
    return a;
}
__device__ __forceinline__ void mma16816(float* d, const u32* a, const u32* b) {
    asm volatile(
        "mma.sync.aligned.m16n8k16.row.col.f32.bf16.bf16.f32 "
        "{%0,%1,%2,%3}, {%4,%5,%6,%7}, {%8,%9}, {%0,%1,%2,%3};"
        : "+f"(d[0]), "+f"(d[1]), "+f"(d[2]), "+f"(d[3])
        : "r"(a[0]), "r"(a[1]), "r"(a[2]), "r"(a[3]), "r"(b[0]), "r"(b[1]));
}
__device__ __forceinline__ void ldsm4(u32* r, u32 addr) {
    asm volatile("ldmatrix.sync.aligned.m8n8.x4.shared.b16 {%0,%1,%2,%3}, [%4];"
                 : "=r"(r[0]), "=r"(r[1]), "=r"(r[2]), "=r"(r[3]) : "r"(addr));
}
__device__ __forceinline__ void ldsm4t(u32* r, u32 addr) {
    asm volatile("ldmatrix.sync.aligned.m8n8.x4.trans.shared.b16 {%0,%1,%2,%3}, [%4];"
                 : "=r"(r[0]), "=r"(r[1]), "=r"(r[2]), "=r"(r[3]) : "r"(addr));
}
__device__ __forceinline__ void split2(float x, float y, u32& hi, u32& lo) {
    asm("cvt.rn.bf16x2.f32 %0, %1, %2;" : "=r"(hi) : "f"(y), "f"(x));
    float rx = x - __uint_as_float(hi << 16);
    float ry = y - __uint_as_float(hi & 0xFFFF0000u);
    asm("cvt.rn.bf16x2.f32 %0, %1, %2;" : "=r"(lo) : "f"(ry), "f"(rx));
}
__device__ __forceinline__ void split_store4(u16* hb, u16* lb, size_t off, float4 v) {
    u32 h0, h1, l0, l1;
    split2(v.x, v.y, h0, l0);
    split2(v.z, v.w, h1, l1);
    *(uint2*)(hb + off) = make_uint2(h0, h1);
    *(uint2*)(lb + off) = make_uint2(l0, l1);
}
__device__ __forceinline__ void cp16(u32 smem, const void* g) {
    asm volatile("cp.async.cg.shared.global [%0], [%1], 16;" :: "r"(smem), "l"(g));
}
#define CP_COMMIT() asm volatile("cp.async.commit_group;" ::: "memory")
#define CP_WAIT1()  asm volatile("cp.async.wait_group 1;" ::: "memory")

// ---------------- one-shot fp32 -> split bf16 ----------------
__global__ void convert_kernel(const float* __restrict__ hs,
                               const float* __restrict__ Wq, const float* __restrict__ Wk,
                               const float* __restrict__ Wv, const float* __restrict__ Wo) {
    const int idx = blockIdx.x * blockDim.x + threadIdx.x;
    const size_t f4 = (size_t)idx * 4;
    if (f4 < NA) {
        float4 v = *(const float4*)(hs + f4);
        split_store4(g_Ah, g_Al, f4, v);
    } else {
        const size_t g = f4 - NA;
        if (g >= NW) return;
        const int row = (int)(g / 896);
        const float* src;
        if (row < 896)       src = Wq + g;
        else if (row < 1024) src = Wk + (g - (size_t)896 * 896);
        else if (row < 1152) src = Wv + (g - (size_t)1024 * 896);
        else                 src = Wo + (g - (size_t)1152 * 896);
        float4 v = *(const float4*)src;
        split_store4(g_Wh, g_Wl, g, v);
    }
}

// ============ GEMM: tile 128x64, 8 warps (4m x 2n, warp 32x32), 2 CTAs/SM ============
// stage bytes: Ah@0(18432), Al@18432, Bh@36864(9216), Bl@46080; stage 55296.
#define G_STAGE 55296
#define G_SMEM  (2 * G_STAGE)

template <int IS_O>
__global__ __launch_bounds__(256, 2)
void tc_gemm(const float* __restrict__ bq, const float* __restrict__ bk,
             const float* __restrict__ bv, float* __restrict__ out)
{
    extern __shared__ char smraw[];
    const u32 smb = smem_u32(smraw);
    const int tid  = threadIdx.x;
    const int wid  = tid >> 5;
    const int lane = tid & 31;
    const int nb   = blockIdx.x;
    const int m0   = blockIdx.y * 128;

    const int wrow0 = (IS_O ? 1152 : 0) + nb * 64;
    const u16* pAh = (IS_O ? g_Oh : g_Ah) + (size_t)m0 * 896;
    const u16* pAl = (IS_O ? g_Ol : g_Al) + (size_t)m0 * 896;
    const u16* pBh = g_Wh + (size_t)wrow0 * 896;
    const u16* pBl = g_Wl + (size_t)wrow0 * 896;

    const int mbase = (wid & 3) * 32;
    const int nbase = (wid >> 2) * 32;

    const int g  = lane >> 3;
    const int l7 = lane & 7;
    const u32 aoffB = (u32)((mbase + (g & 1) * 8 + l7) * 72 + (g >> 1) * 8) * 2;
    const u32 boffB = (u32)((nbase + (g >> 1) * 8 + l7) * 72 + (g & 1) * 8) * 2;

    float acc[2][4][4];
#pragma unroll
    for (int i = 0; i < 2; ++i)
#pragma unroll
        for (int j = 0; j < 4; ++j)
#pragma unroll
            for (int k = 0; k < 4; ++k) acc[i][j][k] = 0.0f;

    auto issue = [&](int chunk, int s) {
        const u32 sb = smb + (u32)s * G_STAGE;
        const int kc0 = chunk * 64;
        // A hi/lo: 128 rows x 8 chunks
#pragma unroll
        for (int buf = 0; buf < 2; ++buf) {
            const u16* src = buf ? pAl : pAh;
#pragma unroll
            for (int t = 0; t < 4; ++t) {
                const int cc  = tid + t * 256;
                const int row = cc >> 3;
                const int col = cc & 7;
                cp16(sb + buf * 18432 + row * 144 + col * 16,
                     src + (size_t)row * 896 + kc0 + col * 8);
            }
        }
        // B hi/lo: 64 rows x 8 chunks
#pragma unroll
        for (int buf = 0; buf < 2; ++buf) {
            const u16* src = buf ? pBl : pBh;
#pragma unroll
            for (int t = 0; t < 2; ++t) {
                const int cc  = tid + t * 256;
                const int row = cc >> 3;
                const int col = cc & 7;
                cp16(sb + 36864 + buf * 9216 + row * 144 + col * 16,
                     src + (size_t)row * 896 + kc0 + col * 8);
            }
        }
    };

    issue(0, 0);
    CP_COMMIT();

    for (int it = 0; it < 14; ++it) {
        if (it + 1 < 14) issue(it + 1, (it + 1) & 1);
        CP_COMMIT();
        CP_WAIT1();
        __syncthreads();

        const u32 stg = smb + (u32)(it & 1) * G_STAGE;
#pragma unroll
        for (int ks = 0; ks < 4; ++ks) {
            u32 ahi[2][4], alo[2][4];
#pragma unroll
            for (int mi = 0; mi < 2; ++mi) {
                const u32 ad = stg + aoffB + (u32)(mi * 16 * 72) * 2 + ks * 32;
                ldsm4(ahi[mi], ad);
                ldsm4(alo[mi], ad + 18432);
            }
            u32 bhi[4][2], blo[4][2];
#pragma unroll
            for (int jp = 0; jp < 2; ++jp) {
                const u32 bd = stg + 36864 + boffB + (u32)(jp * 16 * 72) * 2 + ks * 32;
                u32 t4[4];
                ldsm4(t4, bd);
                bhi[2 * jp][0] = t4[0]; bhi[2 * jp][1] = t4[1];
                bhi[2 * jp + 1][0] = t4[2]; bhi[2 * jp + 1][1] = t4[3];
                ldsm4(t4, bd + 9216);
                blo[2 * jp][0] = t4[0]; blo[2 * jp][1] = t4[1];
                blo[2 * jp + 1][0] = t4[2]; blo[2 * jp + 1][1] = t4[3];
            }
#pragma unroll
            for (int mi = 0; mi < 2; ++mi)
#pragma unroll
                for (int nj = 0; nj < 4; ++nj) {
                    mma16816(acc[mi][nj], ahi[mi], bhi[nj]);
                    mma16816(acc[mi][nj], ahi[mi], blo[nj]);
                    mma16816(acc[mi][nj], alo[mi], bhi[nj]);
                }
        }
        __syncthreads();
    }

    // ---- epilogue ----
    const int qrow = lane >> 2;
    const int qcol = (lane & 3) * 2;
#pragma unroll
    for (int mi = 0; mi < 2; ++mi) {
#pragma unroll
        for (int half = 0; half < 2; ++half) {
            const int r = mbase + mi * 16 + qrow + half * 8;
            const int m = m0 + r;
            const int bb = m >> 11;
            const int ss = m & (SLEN - 1);
#pragma unroll
            for (int nj = 0; nj < 4; ++nj) {
                const int col = nbase + nj * 8 + qcol;
                const float v0 = acc[mi][nj][half * 2];
                const float v1 = acc[mi][nj][half * 2 + 1];
                if (IS_O) {
                    float2 vv; vv.x = v0; vv.y = v1;
                    *(float2*)(out + (size_t)m * HID + nb * 64 + col) = vv;
                } else if (nb < 14) {
                    const int gc = nb * 64 + col;
                    const int h = gc >> 6, d0 = gc & 63;
                    float2 vv;
                    vv.x = v0 + bq[gc];
                    vv.y = v1 + bq[gc + 1];
                    *(float2*)(g_Q + (((size_t)(bb * NH + h)) * SLEN + ss) * HD + d0) = vv;
                } else if (nb < 16) {
                    const int gc = (nb - 14) * 64 + col;
                    const int h = gc >> 6, d0 = gc & 63;
                    float2 vv;
                    vv.x = v0 + bk[gc];
                    vv.y = v1 + bk[gc + 1];
                    *(float2*)(g_K + (((size_t)(bb * NKV + h)) * SLEN + ss) * HD + d0) = vv;
                } else {
                    const int gc = (nb - 16) * 64 + col;
                    const int h = gc >> 6, d0 = gc & 63;
                    u32 hi, lo;
                    split2(v0 + bv[gc], v1 + bv[gc + 1], hi, lo);
                    const size_t off = (((size_t)(bb * NKV + h)) * SLEN + ss) * HD + d0;
                    *(u32*)(g_Vh + off) = hi;
                    *(u32*)(g_Vl + off) = lo;
                }
            }
        }
    }
}

// ---------------- RoPE (fp32 in, split bf16 out; Q scaled by 0.125) ----------------
__global__ void rope_split_kernel(const int* __restrict__ pos_ids) {
    const int QROWS = BATCH * NH * SLEN;
    const int idx  = blockIdx.x * blockDim.x + threadIdx.x;
    const int pair = idx & 31;
    const int row  = idx >> 5;

    const float* base;
    u16 *oh, *ol;
    float scale;
    if (row < QROWS) {
        base = g_Q + (size_t)row * HD;
        oh = g_Qh + (size_t)row * HD;
        ol = g_Ql + (size_t)row * HD;
        scale = 0.125f;
    } else {
        const int r2 = row - QROWS;
        base = g_K + (size_t)r2 * HD;
        oh = g_Kh + (size_t)r2 * HD;
        ol = g_Kl + (size_t)r2 * HD;
        scale = 1.0f;
    }

    const int s   = row & (SLEN - 1);
    const float p = (float)pos_ids[s];
    const float ang = p * g_invf[pair];
    float sn, cs;
    sincosf(ang, &sn, &cs);
    const float x1 = base[pair];
    const float x2 = base[pair + 32];
    const float y1 = (x1 * cs - x2 * sn) * scale;
    const float y2 = (x2 * cs + x1 * sn) * scale;
    u32 hi, lo;
    split2(y1, y2, hi, lo);
    oh[pair]      = (u16)(hi & 0xFFFF);
    oh[pair + 32] = (u16)(hi >> 16);
    ol[pair]      = (u16)(lo & 0xFFFF);
    ol[pair + 32] = (u16)(lo >> 16);
}

// ---------------- Flash attention: BM=128, BN=64, 2 CTAs/SM ----------------
// stage bytes: Kh@0(9216), Kl@9216, Vh@18432, Vl@27648; stage 36864.
#define F_STAGE 36864
#define F_SMEM  (2 * F_STAGE)

__global__ __launch_bounds__(256, 2)
void flash_mma() {
    extern __shared__ char smraw[];
    const u32 smb = smem_u32(smraw);
    const int tid  = threadIdx.x;
    const int wid  = tid >> 5;
    const int lane = tid & 31;

    const int blk = (int)gridDim.x - 1 - (int)blockIdx.x;  // heavy tiles first
    const int h   = blockIdx.y;
    const int b   = blockIdx.z;
    const int qi0 = blk * 128;
    const int kh  = h / NREP;

    const u16* Qh = g_Qh + ((size_t)(b * NH + h)) * SLEN * HD;
    const u16* Ql = g_Ql + ((size_t)(b * NH + h)) * SLEN * HD;
    const size_t kvoff = ((size_t)(b * NKV + kh)) * SLEN * HD;
    const u16* Kh = g_Kh + kvoff;
    const u16* Kl = g_Kl + kvoff;
    const u16* Vh = g_Vh + kvoff;
    const u16* Vl = g_Vl + kvoff;

    const int qr = lane >> 2;
    const int q2 = (lane & 3) * 2;
    const int row0 = qi0 + wid * 16 + qr;

    auto issue = [&](int jt, int s) {
        const u32 sb = smb + (u32)s * F_STAGE;
        const int k0 = jt * 64;
#pragma unroll
        for (int buf = 0; buf < 4; ++buf) {
            const u16* src = (buf == 0) ? Kh : (buf == 1) ? Kl : (buf == 2) ? Vh : Vl;
#pragma unroll
            for (int t = 0; t < 2; ++t) {
                const int cc  = tid + t * 256;
                const int row = cc >> 3;
                const int col = cc & 7;
                cp16(sb + buf * 9216 + row * 144 + col * 16,
                     src + (size_t)(k0 + row) * HD + col * 8);
            }
        }
    };

    issue(0, 0);
    CP_COMMIT();

    u32 qhi[4][4], qlo[4][4];
#pragma unroll
    for (int kk = 0; kk < 4; ++kk) {
#pragma unroll
        for (int part = 0; part < 4; ++part) {
            const int r = row0 + (part & 1) * 8;
            const int c = kk * 16 + q2 + (part & 2) * 4;
            qhi[kk][part] = *(const u32*)(Qh + (size_t)r * HD + c);
            qlo[kk][part] = *(const u32*)(Ql + (size_t)r * HD + c);
        }
    }

    float o[8][4];
#pragma unroll
    for (int i = 0; i < 8; ++i)
#pragma unroll
        for (int c = 0; c < 4; ++c) o[i][c] = 0.0f;
    float mx[2] = {-1e30f, -1e30f};
    float l[2]  = {0.0f, 0.0f};

    const int l7 = lane & 7;
    const int n_add = l7 + ((lane >> 4) & 1) * 8;
    const int k_add = ((lane >> 3) & 1) * 8;
    const int kv_add = l7 + ((lane >> 3) & 1) * 8;
    const int dv_add = ((lane >> 4) & 1) * 8;

    const int jmax = 2 * blk + 1;
    for (int j = 0; j <= jmax; ++j) {
        const int k0 = j * 64;
        if (j < jmax) issue(j + 1, (j + 1) & 1);
        CP_COMMIT();
        CP_WAIT1();
        __syncthreads();

        const u32 stg = smb + (u32)(j & 1) * F_STAGE;

        // ---- S = Q*K^T ----
        float sacc[8][4];
#pragma unroll
        for (int i = 0; i < 8; ++i)
#pragma unroll
            for (int c = 0; c < 4; ++c) sacc[i][c] = 0.0f;

#pragma unroll
        for (int kk = 0; kk < 4; ++kk) {
#pragma unroll
            for (int nbp = 0; nbp < 4; ++nbp) {
                const u32 ad = stg + (u32)((nbp * 16 + n_add) * 72 + k_add) * 2 + kk * 32;
                u32 kh4[4], kl4[4];
                ldsm4(kh4, ad);
                ldsm4(kl4, ad + 9216);
                mma16816(sacc[2 * nbp],     qhi[kk], &kh4[0]);
                mma16816(sacc[2 * nbp],     qhi[kk], &kl4[0]);
                mma16816(sacc[2 * nbp],     qlo[kk], &kh4[0]);
                mma16816(sacc[2 * nbp + 1], qhi[kk], &kh4[2]);
                mma16816(sacc[2 * nbp + 1], qhi[kk], &kl4[2]);
                mma16816(sacc[2 * nbp + 1], qlo[kk], &kh4[2]);
            }
        }

        // ---- causal mask (last two tiles) ----
        if (j >= 2 * blk) {
#pragma unroll
            for (int nb = 0; nb < 8; ++nb) {
                const int colb = k0 + nb * 8 + q2;
#pragma unroll
                for (int c = 0; c < 4; ++c) {
                    const int col = colb + (c & 1);
                    const int row = row0 + (c >> 1) * 8;
                    if (col > row) sacc[nb][c] = -1e30f;
                }
            }
        }

        // ---- online softmax ----
#pragma unroll
        for (int hh = 0; hh < 2; ++hh) {
            float rm = -1e30f;
#pragma unroll
            for (int nb = 0; nb < 8; ++nb)
                rm = fmaxf(rm, fmaxf(sacc[nb][2 * hh], sacc[nb][2 * hh + 1]));
            rm = fmaxf(rm, __shfl_xor_sync(0xffffffffu, rm, 1));
            rm = fmaxf(rm, __shfl_xor_sync(0xffffffffu, rm, 2));

            const float mnew = fmaxf(mx[hh], rm);
            const float corr = __expf(mx[hh] - mnew);
            mx[hh] = mnew;

            float rs = 0.0f;
#pragma unroll
            for (int nb = 0; nb < 8; ++nb) {
                float p0 = __expf(sacc[nb][2 * hh] - mnew);
                float p1 = __expf(sacc[nb][2 * hh + 1] - mnew);
                sacc[nb][2 * hh] = p0;
                sacc[nb][2 * hh + 1] = p1;
                rs += p0 + p1;
            }
            rs += __shfl_xor_sync(0xffffffffu, rs, 1);
            rs += __shfl_xor_sync(0xffffffffu, rs, 2);
            l[hh] = l[hh] * corr + rs;
#pragma unroll
            for (int db = 0; db < 8; ++db) {
                o[db][2 * hh]     *= corr;
                o[db][2 * hh + 1] *= corr;
            }
        }

        // ---- pack P ----
        u32 phi[4][4], plo[4][4];
#pragma unroll
        for (int kk = 0; kk < 4; ++kk) {
            split2(sacc[2 * kk][0],     sacc[2 * kk][1],     phi[kk][0], plo[kk][0]);
            split2(sacc[2 * kk][2],     sacc[2 * kk][3],     phi[kk][1], plo[kk][1]);
            split2(sacc[2 * kk + 1][0], sacc[2 * kk + 1][1], phi[kk][2], plo[kk][2]);
            split2(sacc[2 * kk + 1][2], sacc[2 * kk + 1][3], phi[kk][3], plo[kk][3]);
        }

        // ---- O += P*V ----
#pragma unroll
        for (int kk = 0; kk < 4; ++kk) {
#pragma unroll
            for (int dbp = 0; dbp < 4; ++dbp) {
                const u32 ad = stg + 18432 + (u32)((kk * 16 + kv_add) * 72 + dbp * 16 + dv_add) * 2;
                u32 vh4[4], vl4[4];
                ldsm4t(vh4, ad);
                ldsm4t(vl4, ad + 9216);
                mma16816(o[2 * dbp],     phi[kk], &vh4[0]);
                mma16816(o[2 * dbp],     phi[kk], &vl4[0]);
                mma16816(o[2 * dbp],     plo[kk], &vh4[0]);
                mma16816(o[2 * dbp + 1], phi[kk], &vh4[2]);
                mma16816(o[2 * dbp + 1], phi[kk], &vl4[2]);
                mma16816(o[2 * dbp + 1], plo[kk], &vh4[2]);
            }
        }
        __syncthreads();
    }

    // ---- epilogue: split-bf16 attn output ----
#pragma unroll
    for (int hh = 0; hh < 2; ++hh) {
        const float inv = 1.0f / l[hh];
        const int row = row0 + hh * 8;
        const size_t rb = ((size_t)(b * SLEN) + row) * (NH * HD) + h * HD;
#pragma unroll
        for (int db = 0; db < 8; ++db) {
            u32 hi, lo;
            split2(o[db][2 * hh] * inv, o[db][2 * hh + 1] * inv, hi, lo);
            *(u32*)(g_Oh + rb + db * 8 + q2) = hi;
            *(u32*)(g_Ol + rb + db * 8 + q2) = lo;
        }
    }
}

// ---------------- launch ----------------
extern "C" void kernel_launch(void* const* d_in, const int* in_sizes, int n_in,
                              void* d_out, int out_size) {
    const float* hs  = (const float*)d_in[0];
    const int*   pos = (const int*)d_in[1];
    const float* Wq  = (const float*)d_in[2];
    const float* bq  = (const float*)d_in[3];
    const float* Wk  = (const float*)d_in[4];
    const float* bk  = (const float*)d_in[5];
    const float* Wv  = (const float*)d_in[6];
    const float* bv  = (const float*)d_in[7];
    const float* Wo  = (const float*)d_in[8];
    float* out = (float*)d_out;

    (void)in_sizes; (void)n_in; (void)out_size;

    cudaFuncSetAttribute(tc_gemm<0>, cudaFuncAttributeMaxDynamicSharedMemorySize, G_SMEM);
    cudaFuncSetAttribute(tc_gemm<1>, cudaFuncAttributeMaxDynamicSharedMemorySize, G_SMEM);
    cudaFuncSetAttribute(flash_mma, cudaFuncAttributeMaxDynamicSharedMemorySize, F_SMEM);

    init_invf_kernel<<<1, 32>>>();

    convert_kernel<<<(NA + NW) / 4 / 256, 256>>>(hs, Wq, Wk, Wv, Wo);

    // fused QKV projection: nb 0..13 Q, 14..15 K, 16..17 V
    tc_gemm<0><<<dim3(18, 64), 256, G_SMEM>>>(bq, bk, bv, nullptr);

    {
        const int qrows = BATCH * NH * SLEN;
        const int krows = BATCH * NKV * SLEN;
        const int total = (qrows + krows) * (HD / 2);
        rope_split_kernel<<<total / 256, 256>>>(pos);
    }

    flash_mma<<<dim3(SLEN / 128, NH, BATCH), 256, F_SMEM>>>();

    // O projection -> d_out
    tc_gemm<1><<<dim3(14, 64), 256, G_SMEM>>>(nullptr, nullptr, nullptr, out);
}

// round 11
// speedup vs baseline: 1.2330x; 1.2330x over previous
#include <cuda_runtime.h>
#include <cuda_bf16.h>
#include <cuda_fp16.h>
#include <math.h>

#define BATCH 4
#define SLEN  2048
#define HID   896
#define NH    14
#define NKV   2
#define HD    64
#define NREP  (NH / NKV)

typedef unsigned long long u64;
typedef unsigned int u32;
typedef unsigned short u16;

#define NA (8192 * 896)
#define NW (2048 * 896)
#define NQE (BATCH * NH * SLEN * HD)
#define NKE (BATCH * NKV * SLEN * HD)

// ---------------- scratch ----------------
__device__ float g_Q[NQE];              // fp32 post-GEMM Q (rope input)
__device__ float g_K[NKE];              // fp32 post-GEMM K (rope input)
__device__ u16 g_Ah[NA], g_Al[NA];      // hidden split bf16 (GEMM)
__device__ u16 g_Wh[NW], g_Wl[NW];      // weights split bf16 (GEMM)
__device__ u16 g_Qh[NQE], g_Ql[NQE];    // roped Q*0.125, split fp16
__device__ u16 g_Kh[NKE];               // roped K, fp16 (truncated)
__device__ u16 g_Vh[NKE];               // V, fp16 (truncated)
__device__ u16 g_Oh[NA], g_Ol[NA];      // attn out split bf16 (for O-proj)
__device__ float g_invf[HD / 2];

__global__ void init_invf_kernel() {
    int i = threadIdx.x;
    if (i < HD / 2) g_invf[i] = (float)pow(1.0e6, -(double)i / 32.0);
}

// ================= helpers =================
__device__ __forceinline__ u32 smem_u32(const void* p) {
    u32 a;
    asm("{ .reg .u64 t; cvta.to.shared.u64 t, %1; cvt.u32.u64 %0, t; }" : "=r"(a) : "l"(p));
    return a;
}
// bf16 mma
__device__ __forceinline__ void mma16816(float* d, const u32* a, const u32* b) {
    asm volatile(
        "mma.sync.aligned.m16n8k16.row.col.f32.bf16.bf16.f32 "
        "{%0,%1,%2,%3}, {%4,%5,%6,%7}, {%8,%9}, {%0,%1,%2,%3};"
        : "+f"(d[0]), "+f"(d[1]), "+f"(d[2]), "+f"(d[3])
        : "r"(a[0]), "r"(a[1]), "r"(a[2]), "r"(a[3]), "r"(b[0]), "r"(b[1]));
}
// fp16 mma
__device__ __forceinline__ void mma16816h(float* d, const u32* a, const u32* b) {
    asm volatile(
        "mma.sync.aligned.m16n8k16.row.col.f32.f16.f16.f32 "
        "{%0,%1,%2,%3}, {%4,%5,%6,%7}, {%8,%9}, {%0,%1,%2,%3};"
        : "+f"(d[0]), "+f"(d[1]), "+f"(d[2]), "+f"(d[3])
        : "r"(a[0]), "r"(a[1]), "r"(a[2]), "r"(a[3]), "r"(b[0]), "r"(b[1]));
}
__device__ __forceinline__ void ldsm4(u32* r, u32 addr) {
    asm volatile("ldmatrix.sync.aligned.m8n8.x4.shared.b16 {%0,%1,%2,%3}, [%4];"
                 : "=r"(r[0]), "=r"(r[1]), "=r"(r[2]), "=r"(r[3]) : "r"(addr));
}
__device__ __forceinline__ void ldsm4t(u32* r, u32 addr) {
    asm volatile("ldmatrix.sync.aligned.m8n8.x4.trans.shared.b16 {%0,%1,%2,%3}, [%4];"
                 : "=r"(r[0]), "=r"(r[1]), "=r"(r[2]), "=r"(r[3]) : "r"(addr));
}
// bf16 split (x,y) -> hi pair + residual pair
__device__ __forceinline__ void split2(float x, float y, u32& hi, u32& lo) {
    asm("cvt.rn.bf16x2.f32 %0, %1, %2;" : "=r"(hi) : "f"(y), "f"(x));
    float rx = x - __uint_as_float(hi << 16);
    float ry = y - __uint_as_float(hi & 0xFFFF0000u);
    asm("cvt.rn.bf16x2.f32 %0, %1, %2;" : "=r"(lo) : "f"(ry), "f"(rx));
}
// fp16 split (x,y) -> hi pair + residual pair
__device__ __forceinline__ void split2h(float x, float y, u32& hi, u32& lo) {
    __half2 h = __floats2half2_rn(x, y);     // x low, y high
    float2 f = __half22float2(h);
    __half2 l = __floats2half2_rn(x - f.x, y - f.y);
    hi = *(u32*)&h;
    lo = *(u32*)&l;
}
__device__ __forceinline__ u32 pack2h(float x, float y) {
    __half2 h = __floats2half2_rn(x, y);
    return *(u32*)&h;
}
__device__ __forceinline__ void split_store4(u16* hb, u16* lb, size_t off, float4 v) {
    u32 h0, h1, l0, l1;
    split2(v.x, v.y, h0, l0);
    split2(v.z, v.w, h1, l1);
    *(uint2*)(hb + off) = make_uint2(h0, h1);
    *(uint2*)(lb + off) = make_uint2(l0, l1);
}
__device__ __forceinline__ void cp16(u32 smem, const void* g) {
    asm volatile("cp.async.cg.shared.global [%0], [%1], 16;" :: "r"(smem), "l"(g));
}
#define CP_COMMIT() asm volatile("cp.async.commit_group;" ::: "memory")
#define CP_WAIT1()  asm volatile("cp.async.wait_group 1;" ::: "memory")

// ---------------- one-shot fp32 -> split bf16 (GEMM inputs) ----------------
__global__ void convert_kernel(const float* __restrict__ hs,
                               const float* __restrict__ Wq, const float* __restrict__ Wk,
                               const float* __restrict__ Wv, const float* __restrict__ Wo) {
    const int idx = blockIdx.x * blockDim.x + threadIdx.x;
    const size_t f4 = (size_t)idx * 4;
    if (f4 < NA) {
        float4 v = *(const float4*)(hs + f4);
        split_store4(g_Ah, g_Al, f4, v);
    } else {
        const size_t g = f4 - NA;
        if (g >= NW) return;
        const int row = (int)(g / 896);
        const float* src;
        if (row < 896)       src = Wq + g;
        else if (row < 1024) src = Wk + (g - (size_t)896 * 896);
        else if (row < 1152) src = Wv + (g - (size_t)1024 * 896);
        else                 src = Wo + (g - (size_t)1152 * 896);
        float4 v = *(const float4*)src;
        split_store4(g_Wh, g_Wl, g, v);
    }
}

// ============ GEMM: 128x128 tile, 8 warps (2m x 4n), bf16 3-term (R8 structure) ============
#define G_STAGE 73728
#define G_SMEM  (2 * G_STAGE)

template <int IS_O>
__global__ __launch_bounds__(256, 1)
void tc_gemm(const float* __restrict__ bq, const float* __restrict__ bk,
             const float* __restrict__ bv, float* __restrict__ out)
{
    extern __shared__ char smraw[];
    const u32 smb = smem_u32(smraw);
    const int tid  = threadIdx.x;
    const int wid  = tid >> 5;
    const int lane = tid & 31;
    const int nb   = blockIdx.x;
    const int m0   = blockIdx.y * 128;

    const int wrow0 = IS_O ? (1152 + nb * 128) : (nb * 128);
    const u16* pAh = (IS_O ? g_Oh : g_Ah) + (size_t)m0 * 896;
    const u16* pAl = (IS_O ? g_Ol : g_Al) + (size_t)m0 * 896;
    const u16* pBh = g_Wh + (size_t)wrow0 * 896;
    const u16* pBl = g_Wl + (size_t)wrow0 * 896;

    const int mbase = (wid & 1) * 64;
    const int nbase = (wid >> 1) * 32;

    const int g  = lane >> 3;
    const int l7 = lane & 7;
    const u32 aoffB = (u32)((mbase + (g & 1) * 8 + l7) * 72 + (g >> 1) * 8) * 2;
    const u32 boffB = (u32)((nbase + (g >> 1) * 8 + l7) * 72 + (g & 1) * 8) * 2;

    float acc[4][4][4];
#pragma unroll
    for (int i = 0; i < 4; ++i)
#pragma unroll
        for (int j = 0; j < 4; ++j)
#pragma unroll
            for (int k = 0; k < 4; ++k) acc[i][j][k] = 0.0f;

    auto issue = [&](int chunk, int s) {
        const u32 sb = smb + (u32)s * G_STAGE;
        const int kc0 = chunk * 64;
#pragma unroll
        for (int buf = 0; buf < 4; ++buf) {
            const u16* src = (buf == 0) ? pAh : (buf == 1) ? pAl : (buf == 2) ? pBh : pBl;
#pragma unroll
            for (int t = 0; t < 4; ++t) {
                const int cc  = tid + t * 256;
                const int row = cc >> 3;
                const int col = cc & 7;
                cp16(sb + buf * 18432 + row * 144 + col * 16,
                     src + (size_t)row * 896 + kc0 + col * 8);
            }
        }
    };

    issue(0, 0);
    CP_COMMIT();

    for (int it = 0; it < 14; ++it) {
        if (it + 1 < 14) issue(it + 1, (it + 1) & 1);
        CP_COMMIT();
        CP_WAIT1();
        __syncthreads();

        const u32 stg = smb + (u32)(it & 1) * G_STAGE;
#pragma unroll
        for (int ks = 0; ks < 4; ++ks) {
            u32 ahi[4][4], alo[4][4];
#pragma unroll
            for (int mi = 0; mi < 4; ++mi) {
                const u32 ad = stg + aoffB + (u32)(mi * 16 * 72) * 2 + ks * 32;
                ldsm4(ahi[mi], ad);
                ldsm4(alo[mi], ad + 18432);
            }
            u32 bhi[4][2], blo[4][2];
#pragma unroll
            for (int jp = 0; jp < 2; ++jp) {
                const u32 bd = stg + 36864 + boffB + (u32)(jp * 16 * 72) * 2 + ks * 32;
                u32 t4[4];
                ldsm4(t4, bd);
                bhi[2 * jp][0] = t4[0]; bhi[2 * jp][1] = t4[1];
                bhi[2 * jp + 1][0] = t4[2]; bhi[2 * jp + 1][1] = t4[3];
                ldsm4(t4, bd + 18432);
                blo[2 * jp][0] = t4[0]; blo[2 * jp][1] = t4[1];
                blo[2 * jp + 1][0] = t4[2]; blo[2 * jp + 1][1] = t4[3];
            }
#pragma unroll
            for (int mi = 0; mi < 4; ++mi)
#pragma unroll
                for (int nj = 0; nj < 4; ++nj) {
                    mma16816(acc[mi][nj], ahi[mi], bhi[nj]);
                    mma16816(acc[mi][nj], ahi[mi], blo[nj]);
                    mma16816(acc[mi][nj], alo[mi], bhi[nj]);
                }
        }
        __syncthreads();
    }

    const int qrow = lane >> 2;
    const int qcol = (lane & 3) * 2;
#pragma unroll
    for (int mi = 0; mi < 4; ++mi) {
#pragma unroll
        for (int half = 0; half < 2; ++half) {
            const int r = mbase + mi * 16 + qrow + half * 8;
            const int m = m0 + r;
            const int bb = m >> 11;
            const int ss = m & (SLEN - 1);
#pragma unroll
            for (int nj = 0; nj < 4; ++nj) {
                const int col = nbase + nj * 8 + qcol;
                const float v0 = acc[mi][nj][half * 2];
                const float v1 = acc[mi][nj][half * 2 + 1];
                if (IS_O) {
                    float2 vv; vv.x = v0; vv.y = v1;
                    *(float2*)(out + (size_t)m * HID + nb * 128 + col) = vv;
                } else if (nb < 7) {
                    const int gc = nb * 128 + col;
                    const int h = gc >> 6, d0 = gc & 63;
                    float2 vv;
                    vv.x = v0 + bq[gc];
                    vv.y = v1 + bq[gc + 1];
                    *(float2*)(g_Q + (((size_t)(bb * NH + h)) * SLEN + ss) * HD + d0) = vv;
                } else if (nb == 7) {
                    const int h = col >> 6, d0 = col & 63;
                    float2 vv;
                    vv.x = v0 + bk[col];
                    vv.y = v1 + bk[col + 1];
                    *(float2*)(g_K + (((size_t)(bb * NKV + h)) * SLEN + ss) * HD + d0) = vv;
                } else {
                    const int h = col >> 6, d0 = col & 63;
                    const size_t off = (((size_t)(bb * NKV + h)) * SLEN + ss) * HD + d0;
                    *(u32*)(g_Vh + off) = pack2h(v0 + bv[col], v1 + bv[col + 1]);
                }
            }
        }
    }
}

// ---------------- RoPE: fp32 in; Q -> split fp16 (x0.125), K -> fp16 ----------------
__global__ void rope_split_kernel(const int* __restrict__ pos_ids) {
    const int QROWS = BATCH * NH * SLEN;
    const int idx  = blockIdx.x * blockDim.x + threadIdx.x;
    const int pair = idx & 31;
    const int row  = idx >> 5;

    const int s = row & (SLEN - 1);
    const float p = (float)pos_ids[s];
    const float ang = p * g_invf[pair];
    float sn, cs;
    sincosf(ang, &sn, &cs);

    if (row < QROWS) {
        const float* base = g_Q + (size_t)row * HD;
        const float x1 = base[pair];
        const float x2 = base[pair + 32];
        const float y1 = (x1 * cs - x2 * sn) * 0.125f;
        const float y2 = (x2 * cs + x1 * sn) * 0.125f;
        u16* oh = g_Qh + (size_t)row * HD;
        u16* ol = g_Ql + (size_t)row * HD;
        __half h1 = __float2half_rn(y1);
        __half h2 = __float2half_rn(y2);
        __half l1 = __float2half_rn(y1 - __half2float(h1));
        __half l2 = __float2half_rn(y2 - __half2float(h2));
        oh[pair]      = *(u16*)&h1;
        oh[pair + 32] = *(u16*)&h2;
        ol[pair]      = *(u16*)&l1;
        ol[pair + 32] = *(u16*)&l2;
    } else {
        const int r2 = row - QROWS;
        const float* base = g_K + (size_t)r2 * HD;
        const float x1 = base[pair];
        const float x2 = base[pair + 32];
        const float y1 = x1 * cs - x2 * sn;
        const float y2 = x2 * cs + x1 * sn;
        u16* oh = g_Kh + (size_t)r2 * HD;
        __half h1 = __float2half_rn(y1);
        __half h2 = __float2half_rn(y2);
        oh[pair]      = *(u16*)&h1;
        oh[pair + 32] = *(u16*)&h2;
    }
}

// ---------------- Flash attention: fp16 2-term, BM=128, BN=128 ----------------
// stage bytes: Kh@0 (18432), Vh@18432 (18432); stage 36864; 2 stages.
#define F_STAGE 36864
#define F_SMEM  (2 * F_STAGE)

__global__ __launch_bounds__(256, 1)
void flash_mma() {
    extern __shared__ char smraw[];
    const u32 smb = smem_u32(smraw);
    const int tid  = threadIdx.x;
    const int wid  = tid >> 5;
    const int lane = tid & 31;

    const int blk = (int)gridDim.x - 1 - (int)blockIdx.x;
    const int h   = blockIdx.y;
    const int b   = blockIdx.z;
    const int qi0 = blk * 128;
    const int kh  = h / NREP;

    const u16* Qh = g_Qh + ((size_t)(b * NH + h)) * SLEN * HD;
    const u16* Ql = g_Ql + ((size_t)(b * NH + h)) * SLEN * HD;
    const size_t kvoff = ((size_t)(b * NKV + kh)) * SLEN * HD;
    const u16* Kh = g_Kh + kvoff;
    const u16* Vh = g_Vh + kvoff;

    const int qr = lane >> 2;
    const int q2 = (lane & 3) * 2;
    const int row0 = qi0 + wid * 16 + qr;

    auto issue = [&](int jt, int s) {
        const u32 sb = smb + (u32)s * F_STAGE;
        const int k0 = jt * 128;
#pragma unroll
        for (int buf = 0; buf < 2; ++buf) {
            const u16* src = buf ? Vh : Kh;
#pragma unroll
            for (int t = 0; t < 4; ++t) {
                const int cc  = tid + t * 256;
                const int row = cc >> 3;
                const int col = cc & 7;
                cp16(sb + buf * 18432 + row * 144 + col * 16,
                     src + (size_t)(k0 + row) * HD + col * 8);
            }
        }
    };

    issue(0, 0);
    CP_COMMIT();

    // Q fragments (fp16, pre-scaled, split)
    u32 qhi[4][4], qlo[4][4];
#pragma unroll
    for (int kk = 0; kk < 4; ++kk) {
#pragma unroll
        for (int part = 0; part < 4; ++part) {
            const int r = row0 + (part & 1) * 8;
            const int c = kk * 16 + q2 + (part & 2) * 4;
            qhi[kk][part] = *(const u32*)(Qh + (size_t)r * HD + c);
            qlo[kk][part] = *(const u32*)(Ql + (size_t)r * HD + c);
        }
    }

    float o[8][4];
#pragma unroll
    for (int i = 0; i < 8; ++i)
#pragma unroll
        for (int c = 0; c < 4; ++c) o[i][c] = 0.0f;
    float mx[2] = {-1e30f, -1e30f};
    float l[2]  = {0.0f, 0.0f};

    const int l7 = lane & 7;
    const int n_add = l7 + ((lane >> 4) & 1) * 8;
    const int k_add = ((lane >> 3) & 1) * 8;
    const int kv_add = l7 + ((lane >> 3) & 1) * 8;
    const int dv_add = ((lane >> 4) & 1) * 8;

    for (int j = 0; j <= blk; ++j) {
        const int k0 = j * 128;
        if (j < blk) issue(j + 1, (j + 1) & 1);
        CP_COMMIT();
        CP_WAIT1();
        __syncthreads();

        const u32 stg = smb + (u32)(j & 1) * F_STAGE;

        // ---- S = Q*K^T (fp16: Qh*Kh + Ql*Kh) ----
        float sacc[16][4];
#pragma unroll
        for (int i = 0; i < 16; ++i)
#pragma unroll
            for (int c = 0; c < 4; ++c) sacc[i][c] = 0.0f;

#pragma unroll
        for (int kk = 0; kk < 4; ++kk) {
#pragma unroll
            for (int nbp = 0; nbp < 8; ++nbp) {
                const u32 ad = stg + (u32)((nbp * 16 + n_add) * 72 + k_add) * 2 + kk * 32;
                u32 kh4[4];
                ldsm4(kh4, ad);
                mma16816h(sacc[2 * nbp],     qhi[kk], &kh4[0]);
                mma16816h(sacc[2 * nbp],     qlo[kk], &kh4[0]);
                mma16816h(sacc[2 * nbp + 1], qhi[kk], &kh4[2]);
                mma16816h(sacc[2 * nbp + 1], qlo[kk], &kh4[2]);
            }
        }

        // ---- causal mask ----
        if (j == blk) {
#pragma unroll
            for (int nb = 0; nb < 16; ++nb) {
                const int colb = k0 + nb * 8 + q2;
#pragma unroll
                for (int c = 0; c < 4; ++c) {
                    const int col = colb + (c & 1);
                    const int row = row0 + (c >> 1) * 8;
                    if (col > row) sacc[nb][c] = -1e30f;
                }
            }
        }

        // ---- online softmax ----
#pragma unroll
        for (int hh = 0; hh < 2; ++hh) {
            float rm = -1e30f;
#pragma unroll
            for (int nb = 0; nb < 16; ++nb)
                rm = fmaxf(rm, fmaxf(sacc[nb][2 * hh], sacc[nb][2 * hh + 1]));
            rm = fmaxf(rm, __shfl_xor_sync(0xffffffffu, rm, 1));
            rm = fmaxf(rm, __shfl_xor_sync(0xffffffffu, rm, 2));

            const float mnew = fmaxf(mx[hh], rm);
            const float corr = __expf(mx[hh] - mnew);
            mx[hh] = mnew;

            float rs = 0.0f;
#pragma unroll
            for (int nb = 0; nb < 16; ++nb) {
                float p0 = __expf(sacc[nb][2 * hh] - mnew);
                float p1 = __expf(sacc[nb][2 * hh + 1] - mnew);
                sacc[nb][2 * hh] = p0;
                sacc[nb][2 * hh + 1] = p1;
                rs += p0 + p1;
            }
            rs += __shfl_xor_sync(0xffffffffu, rs, 1);
            rs += __shfl_xor_sync(0xffffffffu, rs, 2);
            l[hh] = l[hh] * corr + rs;
#pragma unroll
            for (int db = 0; db < 8; ++db) {
                o[db][2 * hh]     *= corr;
                o[db][2 * hh + 1] *= corr;
            }
        }

        // ---- pack P (fp16 hi + residual) ----
        u32 phi[8][4], plo[8][4];
#pragma unroll
        for (int kk = 0; kk < 8; ++kk) {
            split2h(sacc[2 * kk][0],     sacc[2 * kk][1],     phi[kk][0], plo[kk][0]);
            split2h(sacc[2 * kk][2],     sacc[2 * kk][3],     phi[kk][1], plo[kk][1]);
            split2h(sacc[2 * kk + 1][0], sacc[2 * kk + 1][1], phi[kk][2], plo[kk][2]);
            split2h(sacc[2 * kk + 1][2], sacc[2 * kk + 1][3], phi[kk][3], plo[kk][3]);
        }

        // ---- O += P*V (fp16: Ph*Vh + Pl*Vh) ----
#pragma unroll
        for (int kk = 0; kk < 8; ++kk) {
#pragma unroll
            for (int dbp = 0; dbp < 4; ++dbp) {
                const u32 ad = stg + 18432 + (u32)((kk * 16 + kv_add) * 72 + dbp * 16 + dv_add) * 2;
                u32 vh4[4];
                ldsm4t(vh4, ad);
                mma16816h(o[2 * dbp],     phi[kk], &vh4[0]);
                mma16816h(o[2 * dbp],     plo[kk], &vh4[0]);
                mma16816h(o[2 * dbp + 1], phi[kk], &vh4[2]);
                mma16816h(o[2 * dbp + 1], plo[kk], &vh4[2]);
            }
        }
        __syncthreads();
    }

    // ---- epilogue: split-bf16 attn output (feeds bf16 O-proj) ----
#pragma unroll
    for (int hh = 0; hh < 2; ++hh) {
        const float inv = 1.0f / l[hh];
        const int row = row0 + hh * 8;
        const size_t rb = ((size_t)(b * SLEN) + row) * (NH * HD) + h * HD;
#pragma unroll
        for (int db = 0; db < 8; ++db) {
            u32 hi, lo;
            split2(o[db][2 * hh] * inv, o[db][2 * hh + 1] * inv, hi, lo);
            *(u32*)(g_Oh + rb + db * 8 + q2) = hi;
            *(u32*)(g_Ol + rb + db * 8 + q2) = lo;
        }
    }
}

// ---------------- launch ----------------
extern "C" void kernel_launch(void* const* d_in, const int* in_sizes, int n_in,
                              void* d_out, int out_size) {
    const float* hs  = (const float*)d_in[0];
    const int*   pos = (const int*)d_in[1];
    const float* Wq  = (const float*)d_in[2];
    const float* bq  = (const float*)d_in[3];
    const float* Wk  = (const float*)d_in[4];
    const float* bk  = (const float*)d_in[5];
    const float* Wv  = (const float*)d_in[6];
    const float* bv  = (const float*)d_in[7];
    const float* Wo  = (const float*)d_in[8];
    float* out = (float*)d_out;

    (void)in_sizes; (void)n_in; (void)out_size;

    cudaFuncSetAttribute(tc_gemm<0>, cudaFuncAttributeMaxDynamicSharedMemorySize, G_SMEM);
    cudaFuncSetAttribute(tc_gemm<1>, cudaFuncAttributeMaxDynamicSharedMemorySize, G_SMEM);
    cudaFuncSetAttribute(flash_mma, cudaFuncAttributeMaxDynamicSharedMemorySize, F_SMEM);

    init_invf_kernel<<<1, 32>>>();

    convert_kernel<<<(NA + NW) / 4 / 256, 256>>>(hs, Wq, Wk, Wv, Wo);

    // fused QKV projection: nb 0..6 Q, 7 K, 8 V
    tc_gemm<0><<<dim3(9, 64), 256, G_SMEM>>>(bq, bk, bv, nullptr);

    {
        const int qrows = BATCH * NH * SLEN;
        const int krows = BATCH * NKV * SLEN;
        const int total = (qrows + krows) * (HD / 2);
        rope_split_kernel<<<total / 256, 256>>>(pos);
    }

    flash_mma<<<dim3(SLEN / 128, NH, BATCH), 256, F_SMEM>>>();

    // O projection -> d_out
    tc_gemm<1><<<dim3(7, 64), 256, G_SMEM>>>(nullptr, nullptr, nullptr, out);
}

// round 12
// speedup vs baseline: 1.4249x; 1.1556x over previous
#include <cuda_runtime.h>
#include <cuda_bf16.h>
#include <cuda_fp16.h>
#include <math.h>

#define BATCH 4
#define SLEN  2048
#define HID   896
#define NH    14
#define NKV   2
#define HD    64
#define NREP  (NH / NKV)

typedef unsigned long long u64;
typedef unsigned int u32;
typedef unsigned short u16;

#define NA (8192 * 896)
#define NW (2048 * 896)
#define NQE (BATCH * NH * SLEN * HD)
#define NKE (BATCH * NKV * SLEN * HD)

// ---------------- scratch ----------------
__device__ float g_Q[NQE];              // fp32 post-GEMM Q (rope input)
__device__ float g_K[NKE];              // fp32 post-GEMM K (rope input)
__device__ u16 g_Ah[NA], g_Al[NA];      // hidden split fp16
__device__ u16 g_Wh[NW];                // weights fp16 (truncated)
__device__ u16 g_Qh[NQE], g_Ql[NQE];    // roped Q*0.125, split fp16
__device__ u16 g_Kh[NKE];               // roped K, fp16
__device__ u16 g_Vh[NKE];               // V, fp16
__device__ u16 g_Oh[NA], g_Ol[NA];      // attn out split fp16 (O-proj A operand)
__device__ float g_invf[HD / 2];

__global__ void init_invf_kernel() {
    int i = threadIdx.x;
    if (i < HD / 2) g_invf[i] = (float)pow(1.0e6, -(double)i / 32.0);
}

// ================= helpers =================
__device__ __forceinline__ u32 smem_u32(const void* p) {
    u32 a;
    asm("{ .reg .u64 t; cvta.to.shared.u64 t, %1; cvt.u32.u64 %0, t; }" : "=r"(a) : "l"(p));
    return a;
}
// fp16 mma
__device__ __forceinline__ void mma16816h(float* d, const u32* a, const u32* b) {
    asm volatile(
        "mma.sync.aligned.m16n8k16.row.col.f32.f16.f16.f32 "
        "{%0,%1,%2,%3}, {%4,%5,%6,%7}, {%8,%9}, {%0,%1,%2,%3};"
        : "+f"(d[0]), "+f"(d[1]), "+f"(d[2]), "+f"(d[3])
        : "r"(a[0]), "r"(a[1]), "r"(a[2]), "r"(a[3]), "r"(b[0]), "r"(b[1]));
}
__device__ __forceinline__ void ldsm4(u32* r, u32 addr) {
    asm volatile("ldmatrix.sync.aligned.m8n8.x4.shared.b16 {%0,%1,%2,%3}, [%4];"
                 : "=r"(r[0]), "=r"(r[1]), "=r"(r[2]), "=r"(r[3]) : "r"(addr));
}
__device__ __forceinline__ void ldsm4t(u32* r, u32 addr) {
    asm volatile("ldmatrix.sync.aligned.m8n8.x4.trans.shared.b16 {%0,%1,%2,%3}, [%4];"
                 : "=r"(r[0]), "=r"(r[1]), "=r"(r[2]), "=r"(r[3]) : "r"(addr));
}
// fp16 split (x,y) -> hi pair + residual pair
__device__ __forceinline__ void split2h(float x, float y, u32& hi, u32& lo) {
    __half2 h = __floats2half2_rn(x, y);
    float2 f = __half22float2(h);
    __half2 l = __floats2half2_rn(x - f.x, y - f.y);
    hi = *(u32*)&h;
    lo = *(u32*)&l;
}
__device__ __forceinline__ u32 pack2h(float x, float y) {
    __half2 h = __floats2half2_rn(x, y);
    return *(u32*)&h;
}
__device__ __forceinline__ void cp16(u32 smem, const void* g) {
    asm volatile("cp.async.cg.shared.global [%0], [%1], 16;" :: "r"(smem), "l"(g));
}
#define CP_COMMIT() asm volatile("cp.async.commit_group;" ::: "memory")
#define CP_WAIT1()  asm volatile("cp.async.wait_group 1;" ::: "memory")

// ---------------- one-shot fp32 -> fp16 conversion ----------------
__global__ void convert_kernel(const float* __restrict__ hs,
                               const float* __restrict__ Wq, const float* __restrict__ Wk,
                               const float* __restrict__ Wv, const float* __restrict__ Wo) {
    const int idx = blockIdx.x * blockDim.x + threadIdx.x;
    const size_t f4 = (size_t)idx * 4;
    if (f4 < NA) {
        float4 v = *(const float4*)(hs + f4);
        u32 h0, h1, l0, l1;
        split2h(v.x, v.y, h0, l0);
        split2h(v.z, v.w, h1, l1);
        *(uint2*)(g_Ah + f4) = make_uint2(h0, h1);
        *(uint2*)(g_Al + f4) = make_uint2(l0, l1);
    } else {
        const size_t g = f4 - NA;
        if (g >= NW) return;
        const int row = (int)(g / 896);
        const float* src;
        if (row < 896)       src = Wq + g;
        else if (row < 1024) src = Wk + (g - (size_t)896 * 896);
        else if (row < 1152) src = Wv + (g - (size_t)1024 * 896);
        else                 src = Wo + (g - (size_t)1152 * 896);
        float4 v = *(const float4*)src;
        *(uint2*)(g_Wh + g) = make_uint2(pack2h(v.x, v.y), pack2h(v.z, v.w));
    }
}

// ============ GEMM: 128x128 tile, 8 warps (2m x 4n), fp16 2-term ============
// stage bytes: Ah@0, Al@18432, Bh@36864; stage 55296; 2 stages.
#define G_STAGE 55296
#define G_SMEM  (2 * G_STAGE)

template <int IS_O>
__global__ __launch_bounds__(256, 1)
void tc_gemm(const float* __restrict__ bq, const float* __restrict__ bk,
             const float* __restrict__ bv, float* __restrict__ out)
{
    extern __shared__ char smraw[];
    const u32 smb = smem_u32(smraw);
    const int tid  = threadIdx.x;
    const int wid  = tid >> 5;
    const int lane = tid & 31;
    const int nb   = blockIdx.x;
    const int m0   = blockIdx.y * 128;

    const int wrow0 = IS_O ? (1152 + nb * 128) : (nb * 128);
    const u16* pAh = (IS_O ? g_Oh : g_Ah) + (size_t)m0 * 896;
    const u16* pAl = (IS_O ? g_Ol : g_Al) + (size_t)m0 * 896;
    const u16* pBh = g_Wh + (size_t)wrow0 * 896;

    const int mbase = (wid & 1) * 64;
    const int nbase = (wid >> 1) * 32;

    const int g  = lane >> 3;
    const int l7 = lane & 7;
    const u32 aoffB = (u32)((mbase + (g & 1) * 8 + l7) * 72 + (g >> 1) * 8) * 2;
    const u32 boffB = (u32)((nbase + (g >> 1) * 8 + l7) * 72 + (g & 1) * 8) * 2;

    float acc[4][4][4];
#pragma unroll
    for (int i = 0; i < 4; ++i)
#pragma unroll
        for (int j = 0; j < 4; ++j)
#pragma unroll
            for (int k = 0; k < 4; ++k) acc[i][j][k] = 0.0f;

    auto issue = [&](int chunk, int s) {
        const u32 sb = smb + (u32)s * G_STAGE;
        const int kc0 = chunk * 64;
#pragma unroll
        for (int buf = 0; buf < 3; ++buf) {
            const u16* src = (buf == 0) ? pAh : (buf == 1) ? pAl : pBh;
#pragma unroll
            for (int t = 0; t < 4; ++t) {
                const int cc  = tid + t * 256;
                const int row = cc >> 3;
                const int col = cc & 7;
                cp16(sb + buf * 18432 + row * 144 + col * 16,
                     src + (size_t)row * 896 + kc0 + col * 8);
            }
        }
    };

    issue(0, 0);
    CP_COMMIT();

    for (int it = 0; it < 14; ++it) {
        if (it + 1 < 14) issue(it + 1, (it + 1) & 1);
        CP_COMMIT();
        CP_WAIT1();
        __syncthreads();

        const u32 stg = smb + (u32)(it & 1) * G_STAGE;
#pragma unroll
        for (int ks = 0; ks < 4; ++ks) {
            u32 ahi[4][4], alo[4][4];
#pragma unroll
            for (int mi = 0; mi < 4; ++mi) {
                const u32 ad = stg + aoffB + (u32)(mi * 16 * 72) * 2 + ks * 32;
                ldsm4(ahi[mi], ad);
                ldsm4(alo[mi], ad + 18432);
            }
            u32 bhi[4][2];
#pragma unroll
            for (int jp = 0; jp < 2; ++jp) {
                const u32 bd = stg + 36864 + boffB + (u32)(jp * 16 * 72) * 2 + ks * 32;
                u32 t4[4];
                ldsm4(t4, bd);
                bhi[2 * jp][0] = t4[0]; bhi[2 * jp][1] = t4[1];
                bhi[2 * jp + 1][0] = t4[2]; bhi[2 * jp + 1][1] = t4[3];
            }
#pragma unroll
            for (int mi = 0; mi < 4; ++mi)
#pragma unroll
                for (int nj = 0; nj < 4; ++nj) {
                    mma16816h(acc[mi][nj], ahi[mi], bhi[nj]);
                    mma16816h(acc[mi][nj], alo[mi], bhi[nj]);
                }
        }
        __syncthreads();
    }

    const int qrow = lane >> 2;
    const int qcol = (lane & 3) * 2;
#pragma unroll
    for (int mi = 0; mi < 4; ++mi) {
#pragma unroll
        for (int half = 0; half < 2; ++half) {
            const int r = mbase + mi * 16 + qrow + half * 8;
            const int m = m0 + r;
            const int bb = m >> 11;
            const int ss = m & (SLEN - 1);
#pragma unroll
            for (int nj = 0; nj < 4; ++nj) {
                const int col = nbase + nj * 8 + qcol;
                const float v0 = acc[mi][nj][half * 2];
                const float v1 = acc[mi][nj][half * 2 + 1];
                if (IS_O) {
                    float2 vv; vv.x = v0; vv.y = v1;
                    *(float2*)(out + (size_t)m * HID + nb * 128 + col) = vv;
                } else if (nb < 7) {
                    const int gc = nb * 128 + col;
                    const int h = gc >> 6, d0 = gc & 63;
                    float2 vv;
                    vv.x = v0 + bq[gc];
                    vv.y = v1 + bq[gc + 1];
                    *(float2*)(g_Q + (((size_t)(bb * NH + h)) * SLEN + ss) * HD + d0) = vv;
                } else if (nb == 7) {
                    const int h = col >> 6, d0 = col & 63;
                    float2 vv;
                    vv.x = v0 + bk[col];
                    vv.y = v1 + bk[col + 1];
                    *(float2*)(g_K + (((size_t)(bb * NKV + h)) * SLEN + ss) * HD + d0) = vv;
                } else {
                    const int h = col >> 6, d0 = col & 63;
                    const size_t off = (((size_t)(bb * NKV + h)) * SLEN + ss) * HD + d0;
                    *(u32*)(g_Vh + off) = pack2h(v0 + bv[col], v1 + bv[col + 1]);
                }
            }
        }
    }
}

// ---------------- RoPE: fp32 in; Q -> split fp16 (x0.125), K -> fp16 ----------------
__global__ void rope_split_kernel(const int* __restrict__ pos_ids) {
    const int QROWS = BATCH * NH * SLEN;
    const int idx  = blockIdx.x * blockDim.x + threadIdx.x;
    const int pair = idx & 31;
    const int row  = idx >> 5;

    const int s = row & (SLEN - 1);
    const float p = (float)pos_ids[s];
    const float ang = p * g_invf[pair];
    float sn, cs;
    sincosf(ang, &sn, &cs);

    if (row < QROWS) {
        const float* base = g_Q + (size_t)row * HD;
        const float x1 = base[pair];
        const float x2 = base[pair + 32];
        const float y1 = (x1 * cs - x2 * sn) * 0.125f;
        const float y2 = (x2 * cs + x1 * sn) * 0.125f;
        u16* oh = g_Qh + (size_t)row * HD;
        u16* ol = g_Ql + (size_t)row * HD;
        __half h1 = __float2half_rn(y1);
        __half h2 = __float2half_rn(y2);
        __half l1 = __float2half_rn(y1 - __half2float(h1));
        __half l2 = __float2half_rn(y2 - __half2float(h2));
        oh[pair]      = *(u16*)&h1;
        oh[pair + 32] = *(u16*)&h2;
        ol[pair]      = *(u16*)&l1;
        ol[pair + 32] = *(u16*)&l2;
    } else {
        const int r2 = row - QROWS;
        const float* base = g_K + (size_t)r2 * HD;
        const float x1 = base[pair];
        const float x2 = base[pair + 32];
        const float y1 = x1 * cs - x2 * sn;
        const float y2 = x2 * cs + x1 * sn;
        u16* oh = g_Kh + (size_t)r2 * HD;
        __half h1 = __float2half_rn(y1);
        __half h2 = __float2half_rn(y2);
        oh[pair]      = *(u16*)&h1;
        oh[pair + 32] = *(u16*)&h2;
    }
}

// ---------------- Flash attention: fp16 2-term, BM=128, BN=128 ----------------
#define F_STAGE 36864
#define F_SMEM  (2 * F_STAGE)

__global__ __launch_bounds__(256, 1)
void flash_mma() {
    extern __shared__ char smraw[];
    const u32 smb = smem_u32(smraw);
    const int tid  = threadIdx.x;
    const int wid  = tid >> 5;
    const int lane = tid & 31;

    const int blk = (int)gridDim.x - 1 - (int)blockIdx.x;
    const int h   = blockIdx.y;
    const int b   = blockIdx.z;
    const int qi0 = blk * 128;
    const int kh  = h / NREP;

    const u16* Qh = g_Qh + ((size_t)(b * NH + h)) * SLEN * HD;
    const u16* Ql = g_Ql + ((size_t)(b * NH + h)) * SLEN * HD;
    const size_t kvoff = ((size_t)(b * NKV + kh)) * SLEN * HD;
    const u16* Kh = g_Kh + kvoff;
    const u16* Vh = g_Vh + kvoff;

    const int qr = lane >> 2;
    const int q2 = (lane & 3) * 2;
    const int row0 = qi0 + wid * 16 + qr;

    auto issue = [&](int jt, int s) {
        const u32 sb = smb + (u32)s * F_STAGE;
        const int k0 = jt * 128;
#pragma unroll
        for (int buf = 0; buf < 2; ++buf) {
            const u16* src = buf ? Vh : Kh;
#pragma unroll
            for (int t = 0; t < 4; ++t) {
                const int cc  = tid + t * 256;
                const int row = cc >> 3;
                const int col = cc & 7;
                cp16(sb + buf * 18432 + row * 144 + col * 16,
                     src + (size_t)(k0 + row) * HD + col * 8);
            }
        }
    };

    issue(0, 0);
    CP_COMMIT();

    u32 qhi[4][4], qlo[4][4];
#pragma unroll
    for (int kk = 0; kk < 4; ++kk) {
#pragma unroll
        for (int part = 0; part < 4; ++part) {
            const int r = row0 + (part & 1) * 8;
            const int c = kk * 16 + q2 + (part & 2) * 4;
            qhi[kk][part] = *(const u32*)(Qh + (size_t)r * HD + c);
            qlo[kk][part] = *(const u32*)(Ql + (size_t)r * HD + c);
        }
    }

    float o[8][4];
#pragma unroll
    for (int i = 0; i < 8; ++i)
#pragma unroll
        for (int c = 0; c < 4; ++c) o[i][c] = 0.0f;
    float mx[2] = {-1e30f, -1e30f};
    float l[2]  = {0.0f, 0.0f};

    const int l7 = lane & 7;
    const int n_add = l7 + ((lane >> 4) & 1) * 8;
    const int k_add = ((lane >> 3) & 1) * 8;
    const int kv_add = l7 + ((lane >> 3) & 1) * 8;
    const int dv_add = ((lane >> 4) & 1) * 8;

    for (int j = 0; j <= blk; ++j) {
        const int k0 = j * 128;
        if (j < blk) issue(j + 1, (j + 1) & 1);
        CP_COMMIT();
        CP_WAIT1();
        __syncthreads();

        const u32 stg = smb + (u32)(j & 1) * F_STAGE;

        // ---- S = Q*K^T ----
        float sacc[16][4];
#pragma unroll
        for (int i = 0; i < 16; ++i)
#pragma unroll
            for (int c = 0; c < 4; ++c) sacc[i][c] = 0.0f;

#pragma unroll
        for (int kk = 0; kk < 4; ++kk) {
#pragma unroll
            for (int nbp = 0; nbp < 8; ++nbp) {
                const u32 ad = stg + (u32)((nbp * 16 + n_add) * 72 + k_add) * 2 + kk * 32;
                u32 kh4[4];
                ldsm4(kh4, ad);
                mma16816h(sacc[2 * nbp],     qhi[kk], &kh4[0]);
                mma16816h(sacc[2 * nbp],     qlo[kk], &kh4[0]);
                mma16816h(sacc[2 * nbp + 1], qhi[kk], &kh4[2]);
                mma16816h(sacc[2 * nbp + 1], qlo[kk], &kh4[2]);
            }
        }

        // ---- causal mask ----
        if (j == blk) {
#pragma unroll
            for (int nb = 0; nb < 16; ++nb) {
                const int colb = k0 + nb * 8 + q2;
#pragma unroll
                for (int c = 0; c < 4; ++c) {
                    const int col = colb + (c & 1);
                    const int row = row0 + (c >> 1) * 8;
                    if (col > row) sacc[nb][c] = -1e30f;
                }
            }
        }

        // ---- online softmax ----
#pragma unroll
        for (int hh = 0; hh < 2; ++hh) {
            float rm = -1e30f;
#pragma unroll
            for (int nb = 0; nb < 16; ++nb)
                rm = fmaxf(rm, fmaxf(sacc[nb][2 * hh], sacc[nb][2 * hh + 1]));
            rm = fmaxf(rm, __shfl_xor_sync(0xffffffffu, rm, 1));
            rm = fmaxf(rm, __shfl_xor_sync(0xffffffffu, rm, 2));

            const float mnew = fmaxf(mx[hh], rm);
            const float corr = __expf(mx[hh] - mnew);
            mx[hh] = mnew;

            float rs = 0.0f;
#pragma unroll
            for (int nb = 0; nb < 16; ++nb) {
                float p0 = __expf(sacc[nb][2 * hh] - mnew);
                float p1 = __expf(sacc[nb][2 * hh + 1] - mnew);
                sacc[nb][2 * hh] = p0;
                sacc[nb][2 * hh + 1] = p1;
                rs += p0 + p1;
            }
            rs += __shfl_xor_sync(0xffffffffu, rs, 1);
            rs += __shfl_xor_sync(0xffffffffu, rs, 2);
            l[hh] = l[hh] * corr + rs;
#pragma unroll
            for (int db = 0; db < 8; ++db) {
                o[db][2 * hh]     *= corr;
                o[db][2 * hh + 1] *= corr;
            }
        }

        // ---- pack P ----
        u32 phi[8][4], plo[8][4];
#pragma unroll
        for (int kk = 0; kk < 8; ++kk) {
            split2h(sacc[2 * kk][0],     sacc[2 * kk][1],     phi[kk][0], plo[kk][0]);
            split2h(sacc[2 * kk][2],     sacc[2 * kk][3],     phi[kk][1], plo[kk][1]);
            split2h(sacc[2 * kk + 1][0], sacc[2 * kk + 1][1], phi[kk][2], plo[kk][2]);
            split2h(sacc[2 * kk + 1][2], sacc[2 * kk + 1][3], phi[kk][3], plo[kk][3]);
        }

        // ---- O += P*V ----
#pragma unroll
        for (int kk = 0; kk < 8; ++kk) {
#pragma unroll
            for (int dbp = 0; dbp < 4; ++dbp) {
                const u32 ad = stg + 18432 + (u32)((kk * 16 + kv_add) * 72 + dbp * 16 + dv_add) * 2;
                u32 vh4[4];
                ldsm4t(vh4, ad);
                mma16816h(o[2 * dbp],     phi[kk], &vh4[0]);
                mma16816h(o[2 * dbp],     plo[kk], &vh4[0]);
                mma16816h(o[2 * dbp + 1], phi[kk], &vh4[2]);
                mma16816h(o[2 * dbp + 1], plo[kk], &vh4[2]);
            }
        }
        __syncthreads();
    }

    // ---- epilogue: split-fp16 attn output (O-proj A operand) ----
#pragma unroll
    for (int hh = 0; hh < 2; ++hh) {
        const float inv = 1.0f / l[hh];
        const int row = row0 + hh * 8;
        const size_t rb = ((size_t)(b * SLEN) + row) * (NH * HD) + h * HD;
#pragma unroll
        for (int db = 0; db < 8; ++db) {
            u32 hi, lo;
            split2h(o[db][2 * hh] * inv, o[db][2 * hh + 1] * inv, hi, lo);
            *(u32*)(g_Oh + rb + db * 8 + q2) = hi;
            *(u32*)(g_Ol + rb + db * 8 + q2) = lo;
        }
    }
}

// ---------------- launch ----------------
extern "C" void kernel_launch(void* const* d_in, const int* in_sizes, int n_in,
                              void* d_out, int out_size) {
    const float* hs  = (const float*)d_in[0];
    const int*   pos = (const int*)d_in[1];
    const float* Wq  = (const float*)d_in[2];
    const float* bq  = (const float*)d_in[3];
    const float* Wk  = (const float*)d_in[4];
    const float* bk  = (const float*)d_in[5];
    const float* Wv  = (const float*)d_in[6];
    const float* bv  = (const float*)d_in[7];
    const float* Wo  = (const float*)d_in[8];
    float* out = (float*)d_out;

    (void)in_sizes; (void)n_in; (void)out_size;

    cudaFuncSetAttribute(tc_gemm<0>, cudaFuncAttributeMaxDynamicSharedMemorySize, G_SMEM);
    cudaFuncSetAttribute(tc_gemm<1>, cudaFuncAttributeMaxDynamicSharedMemorySize, G_SMEM);
    cudaFuncSetAttribute(flash_mma, cudaFuncAttributeMaxDynamicSharedMemorySize, F_SMEM);

    init_invf_kernel<<<1, 32>>>();

    convert_kernel<<<(NA + NW) / 4 / 256, 256>>>(hs, Wq, Wk, Wv, Wo);

    // fused QKV projection: nb 0..6 Q, 7 K, 8 V
    tc_gemm<0><<<dim3(9, 64), 256, G_SMEM>>>(bq, bk, bv, nullptr);

    {
        const int qrows = BATCH * NH * SLEN;
        const int krows = BATCH * NKV * SLEN;
        const int total = (qrows + krows) * (HD / 2);
        rope_split_kernel<<<total / 256, 256>>>(pos);
    }

    flash_mma<<<dim3(SLEN / 128, NH, BATCH), 256, F_SMEM>>>();

    // O projection -> d_out
    tc_gemm<1><<<dim3(7, 64), 256, G_SMEM>>>(nullptr, nullptr, nullptr, out);
}

// round 13
// speedup vs baseline: 1.6713x; 1.1729x over previous
#include <cuda_runtime.h>
#include <cuda_bf16.h>
#include <cuda_fp16.h>
#include <math.h>

#define BATCH 4
#define SLEN  2048
#define HID   896
#define NH    14
#define NKV   2
#define HD    64
#define NREP  (NH / NKV)

typedef unsigned long long u64;
typedef unsigned int u32;
typedef unsigned short u16;

#define NA (8192 * 896)
#define NW (2048 * 896)
#define NQE (BATCH * NH * SLEN * HD)
#define NKE (BATCH * NKV * SLEN * HD)

// ---------------- scratch ----------------
__device__ float g_Q[NQE];              // fp32 post-GEMM Q (rope input)
__device__ float g_K[NKE];              // fp32 post-GEMM K (rope input)
__device__ u16 g_Ah[NA], g_Al[NA];      // hidden split fp16
__device__ u16 g_Wh[NW];                // weights fp16 (truncated)
__device__ u16 g_Qh[NQE];               // roped Q*0.125, fp16 (single-term)
__device__ u16 g_Kh[NKE];               // roped K, fp16
__device__ u16 g_Vh[NKE];               // V, fp16
__device__ u16 g_Oh[NA], g_Ol[NA];      // attn out split fp16 (O-proj A operand)
__device__ float g_invf[HD / 2];

__global__ void init_invf_kernel() {
    int i = threadIdx.x;
    if (i < HD / 2) g_invf[i] = (float)pow(1.0e6, -(double)i / 32.0);
}

// ================= helpers =================
__device__ __forceinline__ u32 smem_u32(const void* p) {
    u32 a;
    asm("{ .reg .u64 t; cvta.to.shared.u64 t, %1; cvt.u32.u64 %0, t; }" : "=r"(a) : "l"(p));
    return a;
}
__device__ __forceinline__ void mma16816h(float* d, const u32* a, const u32* b) {
    asm volatile(
        "mma.sync.aligned.m16n8k16.row.col.f32.f16.f16.f32 "
        "{%0,%1,%2,%3}, {%4,%5,%6,%7}, {%8,%9}, {%0,%1,%2,%3};"
        : "+f"(d[0]), "+f"(d[1]), "+f"(d[2]), "+f"(d[3])
        : "r"(a[0]), "r"(a[1]), "r"(a[2]), "r"(a[3]), "r"(b[0]), "r"(b[1]));
}
__device__ __forceinline__ void ldsm4(u32* r, u32 addr) {
    asm volatile("ldmatrix.sync.aligned.m8n8.x4.shared.b16 {%0,%1,%2,%3}, [%4];"
                 : "=r"(r[0]), "=r"(r[1]), "=r"(r[2]), "=r"(r[3]) : "r"(addr));
}
__device__ __forceinline__ void ldsm4t(u32* r, u32 addr) {
    asm volatile("ldmatrix.sync.aligned.m8n8.x4.trans.shared.b16 {%0,%1,%2,%3}, [%4];"
                 : "=r"(r[0]), "=r"(r[1]), "=r"(r[2]), "=r"(r[3]) : "r"(addr));
}
__device__ __forceinline__ void split2h(float x, float y, u32& hi, u32& lo) {
    __half2 h = __floats2half2_rn(x, y);
    float2 f = __half22float2(h);
    __half2 l = __floats2half2_rn(x - f.x, y - f.y);
    hi = *(u32*)&h;
    lo = *(u32*)&l;
}
__device__ __forceinline__ u32 pack2h(float x, float y) {
    __half2 h = __floats2half2_rn(x, y);
    return *(u32*)&h;
}
__device__ __forceinline__ void cp16(u32 smem, const void* g) {
    asm volatile("cp.async.cg.shared.global [%0], [%1], 16;" :: "r"(smem), "l"(g));
}
#define CP_COMMIT() asm volatile("cp.async.commit_group;" ::: "memory")
#define CP_WAIT1()  asm volatile("cp.async.wait_group 1;" ::: "memory")

// ---------------- one-shot fp32 -> fp16 conversion ----------------
__global__ void convert_kernel(const float* __restrict__ hs,
                               const float* __restrict__ Wq, const float* __restrict__ Wk,
                               const float* __restrict__ Wv, const float* __restrict__ Wo) {
    const int idx = blockIdx.x * blockDim.x + threadIdx.x;
    const size_t f4 = (size_t)idx * 4;
    if (f4 < NA) {
        float4 v = *(const float4*)(hs + f4);
        u32 h0, h1, l0, l1;
        split2h(v.x, v.y, h0, l0);
        split2h(v.z, v.w, h1, l1);
        *(uint2*)(g_Ah + f4) = make_uint2(h0, h1);
        *(uint2*)(g_Al + f4) = make_uint2(l0, l1);
    } else {
        const size_t g = f4 - NA;
        if (g >= NW) return;
        const int row = (int)(g / 896);
        const float* src;
        if (row < 896)       src = Wq + g;
        else if (row < 1024) src = Wk + (g - (size_t)896 * 896);
        else if (row < 1152) src = Wv + (g - (size_t)1024 * 896);
        else                 src = Wo + (g - (size_t)1152 * 896);
        float4 v = *(const float4*)src;
        *(uint2*)(g_Wh + g) = make_uint2(pack2h(v.x, v.y), pack2h(v.z, v.w));
    }
}

// ============ GEMM: 128x128 tile, 8 warps (2m x 4n), fp16 2-term A ============
#define G_STAGE 55296
#define G_SMEM  (2 * G_STAGE)

template <int IS_O>
__global__ __launch_bounds__(256, 1)
void tc_gemm(const float* __restrict__ bq, const float* __restrict__ bk,
             const float* __restrict__ bv, float* __restrict__ out)
{
    extern __shared__ char smraw[];
    const u32 smb = smem_u32(smraw);
    const int tid  = threadIdx.x;
    const int wid  = tid >> 5;
    const int lane = tid & 31;
    const int nb   = blockIdx.x;
    const int m0   = blockIdx.y * 128;

    const int wrow0 = IS_O ? (1152 + nb * 128) : (nb * 128);
    const u16* pAh = (IS_O ? g_Oh : g_Ah) + (size_t)m0 * 896;
    const u16* pAl = (IS_O ? g_Ol : g_Al) + (size_t)m0 * 896;
    const u16* pBh = g_Wh + (size_t)wrow0 * 896;

    const int mbase = (wid & 1) * 64;
    const int nbase = (wid >> 1) * 32;

    const int g  = lane >> 3;
    const int l7 = lane & 7;
    const u32 aoffB = (u32)((mbase + (g & 1) * 8 + l7) * 72 + (g >> 1) * 8) * 2;
    const u32 boffB = (u32)((nbase + (g >> 1) * 8 + l7) * 72 + (g & 1) * 8) * 2;

    float acc[4][4][4];
#pragma unroll
    for (int i = 0; i < 4; ++i)
#pragma unroll
        for (int j = 0; j < 4; ++j)
#pragma unroll
            for (int k = 0; k < 4; ++k) acc[i][j][k] = 0.0f;

    auto issue = [&](int chunk, int s) {
        const u32 sb = smb + (u32)s * G_STAGE;
        const int kc0 = chunk * 64;
#pragma unroll
        for (int buf = 0; buf < 3; ++buf) {
            const u16* src = (buf == 0) ? pAh : (buf == 1) ? pAl : pBh;
#pragma unroll
            for (int t = 0; t < 4; ++t) {
                const int cc  = tid + t * 256;
                const int row = cc >> 3;
                const int col = cc & 7;
                cp16(sb + buf * 18432 + row * 144 + col * 16,
                     src + (size_t)row * 896 + kc0 + col * 8);
            }
        }
    };

    issue(0, 0);
    CP_COMMIT();

    for (int it = 0; it < 14; ++it) {
        if (it + 1 < 14) issue(it + 1, (it + 1) & 1);
        CP_COMMIT();
        CP_WAIT1();
        __syncthreads();

        const u32 stg = smb + (u32)(it & 1) * G_STAGE;
#pragma unroll
        for (int ks = 0; ks < 4; ++ks) {
            u32 ahi[4][4], alo[4][4];
#pragma unroll
            for (int mi = 0; mi < 4; ++mi) {
                const u32 ad = stg + aoffB + (u32)(mi * 16 * 72) * 2 + ks * 32;
                ldsm4(ahi[mi], ad);
                ldsm4(alo[mi], ad + 18432);
            }
            u32 bhi[4][2];
#pragma unroll
            for (int jp = 0; jp < 2; ++jp) {
                const u32 bd = stg + 36864 + boffB + (u32)(jp * 16 * 72) * 2 + ks * 32;
                u32 t4[4];
                ldsm4(t4, bd);
                bhi[2 * jp][0] = t4[0]; bhi[2 * jp][1] = t4[1];
                bhi[2 * jp + 1][0] = t4[2]; bhi[2 * jp + 1][1] = t4[3];
            }
#pragma unroll
            for (int mi = 0; mi < 4; ++mi)
#pragma unroll
                for (int nj = 0; nj < 4; ++nj) {
                    mma16816h(acc[mi][nj], ahi[mi], bhi[nj]);
                    mma16816h(acc[mi][nj], alo[mi], bhi[nj]);
                }
        }
        __syncthreads();
    }

    const int qrow = lane >> 2;
    const int qcol = (lane & 3) * 2;
#pragma unroll
    for (int mi = 0; mi < 4; ++mi) {
#pragma unroll
        for (int half = 0; half < 2; ++half) {
            const int r = mbase + mi * 16 + qrow + half * 8;
            const int m = m0 + r;
            const int bb = m >> 11;
            const int ss = m & (SLEN - 1);
#pragma unroll
            for (int nj = 0; nj < 4; ++nj) {
                const int col = nbase + nj * 8 + qcol;
                const float v0 = acc[mi][nj][half * 2];
                const float v1 = acc[mi][nj][half * 2 + 1];
                if (IS_O) {
                    float2 vv; vv.x = v0; vv.y = v1;
                    *(float2*)(out + (size_t)m * HID + nb * 128 + col) = vv;
                } else if (nb < 7) {
                    const int gc = nb * 128 + col;
                    const int h = gc >> 6, d0 = gc & 63;
                    float2 vv;
                    vv.x = v0 + bq[gc];
                    vv.y = v1 + bq[gc + 1];
                    *(float2*)(g_Q + (((size_t)(bb * NH + h)) * SLEN + ss) * HD + d0) = vv;
                } else if (nb == 7) {
                    const int h = col >> 6, d0 = col & 63;
                    float2 vv;
                    vv.x = v0 + bk[col];
                    vv.y = v1 + bk[col + 1];
                    *(float2*)(g_K + (((size_t)(bb * NKV + h)) * SLEN + ss) * HD + d0) = vv;
                } else {
                    const int h = col >> 6, d0 = col & 63;
                    const size_t off = (((size_t)(bb * NKV + h)) * SLEN + ss) * HD + d0;
                    *(u32*)(g_Vh + off) = pack2h(v0 + bv[col], v1 + bv[col + 1]);
                }
            }
        }
    }
}

// ---------------- RoPE: fp32 in; Q -> fp16 (x0.125), K -> fp16 ----------------
__global__ void rope_split_kernel(const int* __restrict__ pos_ids) {
    const int QROWS = BATCH * NH * SLEN;
    const int idx  = blockIdx.x * blockDim.x + threadIdx.x;
    const int pair = idx & 31;
    const int row  = idx >> 5;

    const int s = row & (SLEN - 1);
    const float p = (float)pos_ids[s];
    const float ang = p * g_invf[pair];
    float sn, cs;
    sincosf(ang, &sn, &cs);

    if (row < QROWS) {
        const float* base = g_Q + (size_t)row * HD;
        const float x1 = base[pair];
        const float x2 = base[pair + 32];
        const float y1 = (x1 * cs - x2 * sn) * 0.125f;
        const float y2 = (x2 * cs + x1 * sn) * 0.125f;
        u16* oh = g_Qh + (size_t)row * HD;
        __half h1 = __float2half_rn(y1);
        __half h2 = __float2half_rn(y2);
        oh[pair]      = *(u16*)&h1;
        oh[pair + 32] = *(u16*)&h2;
    } else {
        const int r2 = row - QROWS;
        const float* base = g_K + (size_t)r2 * HD;
        const float x1 = base[pair];
        const float x2 = base[pair + 32];
        const float y1 = x1 * cs - x2 * sn;
        const float y2 = x2 * cs + x1 * sn;
        u16* oh = g_Kh + (size_t)r2 * HD;
        __half h1 = __float2half_rn(y1);
        __half h2 = __float2half_rn(y2);
        oh[pair]      = *(u16*)&h1;
        oh[pair + 32] = *(u16*)&h2;
    }
}

// ---------------- Flash attention: single-term fp16, BM=128, BN=128 ----------------
#define F_STAGE 36864
#define F_SMEM  (2 * F_STAGE)

__global__ __launch_bounds__(256, 1)
void flash_mma() {
    extern __shared__ char smraw[];
    const u32 smb = smem_u32(smraw);
    const int tid  = threadIdx.x;
    const int wid  = tid >> 5;
    const int lane = tid & 31;

    const int blk = (int)gridDim.x - 1 - (int)blockIdx.x;
    const int h   = blockIdx.y;
    const int b   = blockIdx.z;
    const int qi0 = blk * 128;
    const int kh  = h / NREP;

    const u16* Qh = g_Qh + ((size_t)(b * NH + h)) * SLEN * HD;
    const size_t kvoff = ((size_t)(b * NKV + kh)) * SLEN * HD;
    const u16* Kh = g_Kh + kvoff;
    const u16* Vh = g_Vh + kvoff;

    const int qr = lane >> 2;
    const int q2 = (lane & 3) * 2;
    const int row0 = qi0 + wid * 16 + qr;

    auto issue = [&](int jt, int s) {
        const u32 sb = smb + (u32)s * F_STAGE;
        const int k0 = jt * 128;
#pragma unroll
        for (int buf = 0; buf < 2; ++buf) {
            const u16* src = buf ? Vh : Kh;
#pragma unroll
            for (int t = 0; t < 4; ++t) {
                const int cc  = tid + t * 256;
                const int row = cc >> 3;
                const int col = cc & 7;
                cp16(sb + buf * 18432 + row * 144 + col * 16,
                     src + (size_t)(k0 + row) * HD + col * 8);
            }
        }
    };

    issue(0, 0);
    CP_COMMIT();

    u32 qhi[4][4];
#pragma unroll
    for (int kk = 0; kk < 4; ++kk) {
#pragma unroll
        for (int part = 0; part < 4; ++part) {
            const int r = row0 + (part & 1) * 8;
            const int c = kk * 16 + q2 + (part & 2) * 4;
            qhi[kk][part] = *(const u32*)(Qh + (size_t)r * HD + c);
        }
    }

    float o[8][4];
#pragma unroll
    for (int i = 0; i < 8; ++i)
#pragma unroll
        for (int c = 0; c < 4; ++c) o[i][c] = 0.0f;
    float mx[2] = {-1e30f, -1e30f};
    float l[2]  = {0.0f, 0.0f};

    const int l7 = lane & 7;
    const int n_add = l7 + ((lane >> 4) & 1) * 8;
    const int k_add = ((lane >> 3) & 1) * 8;
    const int kv_add = l7 + ((lane >> 3) & 1) * 8;
    const int dv_add = ((lane >> 4) & 1) * 8;

    for (int j = 0; j <= blk; ++j) {
        const int k0 = j * 128;
        if (j < blk) issue(j + 1, (j + 1) & 1);
        CP_COMMIT();
        CP_WAIT1();
        __syncthreads();

        const u32 stg = smb + (u32)(j & 1) * F_STAGE;

        // ---- S = Q*K^T (single-term fp16) ----
        float sacc[16][4];
#pragma unroll
        for (int i = 0; i < 16; ++i)
#pragma unroll
            for (int c = 0; c < 4; ++c) sacc[i][c] = 0.0f;

#pragma unroll
        for (int kk = 0; kk < 4; ++kk) {
#pragma unroll
            for (int nbp = 0; nbp < 8; ++nbp) {
                const u32 ad = stg + (u32)((nbp * 16 + n_add) * 72 + k_add) * 2 + kk * 32;
                u32 kh4[4];
                ldsm4(kh4, ad);
                mma16816h(sacc[2 * nbp],     qhi[kk], &kh4[0]);
                mma16816h(sacc[2 * nbp + 1], qhi[kk], &kh4[2]);
            }
        }

        // ---- causal mask ----
        if (j == blk) {
#pragma unroll
            for (int nb = 0; nb < 16; ++nb) {
                const int colb = k0 + nb * 8 + q2;
#pragma unroll
                for (int c = 0; c < 4; ++c) {
                    const int col = colb + (c & 1);
                    const int row = row0 + (c >> 1) * 8;
                    if (col > row) sacc[nb][c] = -1e30f;
                }
            }
        }

        // ---- online softmax ----
#pragma unroll
        for (int hh = 0; hh < 2; ++hh) {
            float rm = -1e30f;
#pragma unroll
            for (int nb = 0; nb < 16; ++nb)
                rm = fmaxf(rm, fmaxf(sacc[nb][2 * hh], sacc[nb][2 * hh + 1]));
            rm = fmaxf(rm, __shfl_xor_sync(0xffffffffu, rm, 1));
            rm = fmaxf(rm, __shfl_xor_sync(0xffffffffu, rm, 2));

            const float mnew = fmaxf(mx[hh], rm);
            const float corr = __expf(mx[hh] - mnew);
            mx[hh] = mnew;

            float rs = 0.0f;
#pragma unroll
            for (int nb = 0; nb < 16; ++nb) {
                float p0 = __expf(sacc[nb][2 * hh] - mnew);
                float p1 = __expf(sacc[nb][2 * hh + 1] - mnew);
                sacc[nb][2 * hh] = p0;
                sacc[nb][2 * hh + 1] = p1;
                rs += p0 + p1;
            }
            rs += __shfl_xor_sync(0xffffffffu, rs, 1);
            rs += __shfl_xor_sync(0xffffffffu, rs, 2);
            l[hh] = l[hh] * corr + rs;
#pragma unroll
            for (int db = 0; db < 8; ++db) {
                o[db][2 * hh]     *= corr;
                o[db][2 * hh + 1] *= corr;
            }
        }

        // ---- pack P (single fp16) ----
        u32 phi[8][4];
#pragma unroll
        for (int kk = 0; kk < 8; ++kk) {
            phi[kk][0] = pack2h(sacc[2 * kk][0],     sacc[2 * kk][1]);
            phi[kk][1] = pack2h(sacc[2 * kk][2],     sacc[2 * kk][3]);
            phi[kk][2] = pack2h(sacc[2 * kk + 1][0], sacc[2 * kk + 1][1]);
            phi[kk][3] = pack2h(sacc[2 * kk + 1][2], sacc[2 * kk + 1][3]);
        }

        // ---- O += P*V (single-term) ----
#pragma unroll
        for (int kk = 0; kk < 8; ++kk) {
#pragma unroll
            for (int dbp = 0; dbp < 4; ++dbp) {
                const u32 ad = stg + 18432 + (u32)((kk * 16 + kv_add) * 72 + dbp * 16 + dv_add) * 2;
                u32 vh4[4];
                ldsm4t(vh4, ad);
                mma16816h(o[2 * dbp],     phi[kk], &vh4[0]);
                mma16816h(o[2 * dbp + 1], phi[kk], &vh4[2]);
            }
        }
        __syncthreads();
    }

    // ---- epilogue: split-fp16 attn output (O-proj A operand, 2-term kept) ----
#pragma unroll
    for (int hh = 0; hh < 2; ++hh) {
        const float inv = 1.0f / l[hh];
        const int row = row0 + hh * 8;
        const size_t rb = ((size_t)(b * SLEN) + row) * (NH * HD) + h * HD;
#pragma unroll
        for (int db = 0; db < 8; ++db) {
            u32 hi, lo;
            split2h(o[db][2 * hh] * inv, o[db][2 * hh + 1] * inv, hi, lo);
            *(u32*)(g_Oh + rb + db * 8 + q2) = hi;
            *(u32*)(g_Ol + rb + db * 8 + q2) = lo;
        }
    }
}

// ---------------- launch ----------------
extern "C" void kernel_launch(void* const* d_in, const int* in_sizes, int n_in,
                              void* d_out, int out_size) {
    const float* hs  = (const float*)d_in[0];
    const int*   pos = (const int*)d_in[1];
    const float* Wq  = (const float*)d_in[2];
    const float* bq  = (const float*)d_in[3];
    const float* Wk  = (const float*)d_in[4];
    const float* bk  = (const float*)d_in[5];
    const float* Wv  = (const float*)d_in[6];
    const float* bv  = (const float*)d_in[7];
    const float* Wo  = (const float*)d_in[8];
    float* out = (float*)d_out;

    (void)in_sizes; (void)n_in; (void)out_size;

    cudaFuncSetAttribute(tc_gemm<0>, cudaFuncAttributeMaxDynamicSharedMemorySize, G_SMEM);
    cudaFuncSetAttribute(tc_gemm<1>, cudaFuncAttributeMaxDynamicSharedMemorySize, G_SMEM);
    cudaFuncSetAttribute(flash_mma, cudaFuncAttributeMaxDynamicSharedMemorySize, F_SMEM);

    init_invf_kernel<<<1, 32>>>();

    convert_kernel<<<(NA + NW) / 4 / 256, 256>>>(hs, Wq, Wk, Wv, Wo);

    // fused QKV projection: nb 0..6 Q, 7 K, 8 V
    tc_gemm<0><<<dim3(9, 64), 256, G_SMEM>>>(bq, bk, bv, nullptr);

    {
        const int qrows = BATCH * NH * SLEN;
        const int krows = BATCH * NKV * SLEN;
        const int total = (qrows + krows) * (HD / 2);
        rope_split_kernel<<<total / 256, 256>>>(pos);
    }

    flash_mma<<<dim3(SLEN / 128, NH, BATCH), 256, F_SMEM>>>();

    // O projection -> d_out
    tc_gemm<1><<<dim3(7, 64), 256, G_SMEM>>>(nullptr, nullptr, nullptr, out);
}

// round 14
// speedup vs baseline: 2.0779x; 1.2433x over previous
#include <cuda_runtime.h>
#include <cuda_bf16.h>
#include <cuda_fp16.h>
#include <math.h>

#define BATCH 4
#define SLEN  2048
#define HID   896
#define NH    14
#define NKV   2
#define HD    64
#define NREP  (NH / NKV)

typedef unsigned long long u64;
typedef unsigned int u32;
typedef unsigned short u16;

#define NA (8192 * 896)
#define NW (2048 * 896)
#define NQE (BATCH * NH * SLEN * HD)
#define NKE (BATCH * NKV * SLEN * HD)

// ---------------- scratch ----------------
__device__ float g_Q[NQE];              // fp32 post-GEMM Q (rope input)
__device__ float g_K[NKE];              // fp32 post-GEMM K (rope input)
__device__ u16 g_Ah[NA];                // hidden fp16
__device__ u16 g_Wh[NW];                // weights fp16
__device__ u16 g_Qh[NQE];               // roped Q*0.125, fp16
__device__ u16 g_Kh[NKE];               // roped K, fp16
__device__ u16 g_Vh[NKE];               // V, fp16
__device__ u16 g_Oh[NA];                // attn out fp16 (O-proj A operand)
__device__ float g_invf[HD / 2];

__global__ void init_invf_kernel() {
    int i = threadIdx.x;
    if (i < HD / 2) g_invf[i] = (float)pow(1.0e6, -(double)i / 32.0);
}

// ================= helpers =================
__device__ __forceinline__ u32 smem_u32(const void* p) {
    u32 a;
    asm("{ .reg .u64 t; cvta.to.shared.u64 t, %1; cvt.u32.u64 %0, t; }" : "=r"(a) : "l"(p));
    return a;
}
__device__ __forceinline__ void mma16816h(float* d, const u32* a, const u32* b) {
    asm volatile(
        "mma.sync.aligned.m16n8k16.row.col.f32.f16.f16.f32 "
        "{%0,%1,%2,%3}, {%4,%5,%6,%7}, {%8,%9}, {%0,%1,%2,%3};"
        : "+f"(d[0]), "+f"(d[1]), "+f"(d[2]), "+f"(d[3])
        : "r"(a[0]), "r"(a[1]), "r"(a[2]), "r"(a[3]), "r"(b[0]), "r"(b[1]));
}
__device__ __forceinline__ void ldsm4(u32* r, u32 addr) {
    asm volatile("ldmatrix.sync.aligned.m8n8.x4.shared.b16 {%0,%1,%2,%3}, [%4];"
                 : "=r"(r[0]), "=r"(r[1]), "=r"(r[2]), "=r"(r[3]) : "r"(addr));
}
__device__ __forceinline__ void ldsm4t(u32* r, u32 addr) {
    asm volatile("ldmatrix.sync.aligned.m8n8.x4.trans.shared.b16 {%0,%1,%2,%3}, [%4];"
                 : "=r"(r[0]), "=r"(r[1]), "=r"(r[2]), "=r"(r[3]) : "r"(addr));
}
__device__ __forceinline__ u32 pack2h(float x, float y) {
    __half2 h = __floats2half2_rn(x, y);
    return *(u32*)&h;
}
__device__ __forceinline__ void cp16(u32 smem, const void* g) {
    asm volatile("cp.async.cg.shared.global [%0], [%1], 16;" :: "r"(smem), "l"(g));
}
#define CP_COMMIT() asm volatile("cp.async.commit_group;" ::: "memory")
#define CP_WAIT1()  asm volatile("cp.async.wait_group 1;" ::: "memory")

// ---------------- one-shot fp32 -> fp16 conversion ----------------
__global__ void convert_kernel(const float* __restrict__ hs,
                               const float* __restrict__ Wq, const float* __restrict__ Wk,
                               const float* __restrict__ Wv, const float* __restrict__ Wo) {
    const int idx = blockIdx.x * blockDim.x + threadIdx.x;
    const size_t f4 = (size_t)idx * 4;
    if (f4 < NA) {
        float4 v = *(const float4*)(hs + f4);
        *(uint2*)(g_Ah + f4) = make_uint2(pack2h(v.x, v.y), pack2h(v.z, v.w));
    } else {
        const size_t g = f4 - NA;
        if (g >= NW) return;
        const int row = (int)(g / 896);
        const float* src;
        if (row < 896)       src = Wq + g;
        else if (row < 1024) src = Wk + (g - (size_t)896 * 896);
        else if (row < 1152) src = Wv + (g - (size_t)1024 * 896);
        else                 src = Wo + (g - (size_t)1152 * 896);
        float4 v = *(const float4*)src;
        *(uint2*)(g_Wh + g) = make_uint2(pack2h(v.x, v.y), pack2h(v.z, v.w));
    }
}

// ============ GEMM: 128x128 tile, 8 warps (2m x 4n), single-term fp16 ============
// stage bytes: Ah@0, Bh@18432; stage 36864; 2 stages.
#define G_STAGE 36864
#define G_SMEM  (2 * G_STAGE)

template <int IS_O>
__global__ __launch_bounds__(256, 1)
void tc_gemm(const float* __restrict__ bq, const float* __restrict__ bk,
             const float* __restrict__ bv, float* __restrict__ out)
{
    extern __shared__ char smraw[];
    const u32 smb = smem_u32(smraw);
    const int tid  = threadIdx.x;
    const int wid  = tid >> 5;
    const int lane = tid & 31;
    const int nb   = blockIdx.x;
    const int m0   = blockIdx.y * 128;

    const int wrow0 = IS_O ? (1152 + nb * 128) : (nb * 128);
    const u16* pAh = (IS_O ? g_Oh : g_Ah) + (size_t)m0 * 896;
    const u16* pBh = g_Wh + (size_t)wrow0 * 896;

    const int mbase = (wid & 1) * 64;
    const int nbase = (wid >> 1) * 32;

    const int g  = lane >> 3;
    const int l7 = lane & 7;
    const u32 aoffB = (u32)((mbase + (g & 1) * 8 + l7) * 72 + (g >> 1) * 8) * 2;
    const u32 boffB = (u32)((nbase + (g >> 1) * 8 + l7) * 72 + (g & 1) * 8) * 2;

    float acc[4][4][4];
#pragma unroll
    for (int i = 0; i < 4; ++i)
#pragma unroll
        for (int j = 0; j < 4; ++j)
#pragma unroll
            for (int k = 0; k < 4; ++k) acc[i][j][k] = 0.0f;

    auto issue = [&](int chunk, int s) {
        const u32 sb = smb + (u32)s * G_STAGE;
        const int kc0 = chunk * 64;
#pragma unroll
        for (int buf = 0; buf < 2; ++buf) {
            const u16* src = buf ? pBh : pAh;
#pragma unroll
            for (int t = 0; t < 4; ++t) {
                const int cc  = tid + t * 256;
                const int row = cc >> 3;
                const int col = cc & 7;
                cp16(sb + buf * 18432 + row * 144 + col * 16,
                     src + (size_t)row * 896 + kc0 + col * 8);
            }
        }
    };

    issue(0, 0);
    CP_COMMIT();

    for (int it = 0; it < 14; ++it) {
        if (it + 1 < 14) issue(it + 1, (it + 1) & 1);
        CP_COMMIT();
        CP_WAIT1();
        __syncthreads();

        const u32 stg = smb + (u32)(it & 1) * G_STAGE;
#pragma unroll
        for (int ks = 0; ks < 4; ++ks) {
            u32 ahi[4][4];
#pragma unroll
            for (int mi = 0; mi < 4; ++mi) {
                const u32 ad = stg + aoffB + (u32)(mi * 16 * 72) * 2 + ks * 32;
                ldsm4(ahi[mi], ad);
            }
            u32 bhi[4][2];
#pragma unroll
            for (int jp = 0; jp < 2; ++jp) {
                const u32 bd = stg + 18432 + boffB + (u32)(jp * 16 * 72) * 2 + ks * 32;
                u32 t4[4];
                ldsm4(t4, bd);
                bhi[2 * jp][0] = t4[0]; bhi[2 * jp][1] = t4[1];
                bhi[2 * jp + 1][0] = t4[2]; bhi[2 * jp + 1][1] = t4[3];
            }
#pragma unroll
            for (int mi = 0; mi < 4; ++mi)
#pragma unroll
                for (int nj = 0; nj < 4; ++nj)
                    mma16816h(acc[mi][nj], ahi[mi], bhi[nj]);
        }
        __syncthreads();
    }

    const int qrow = lane >> 2;
    const int qcol = (lane & 3) * 2;
#pragma unroll
    for (int mi = 0; mi < 4; ++mi) {
#pragma unroll
        for (int half = 0; half < 2; ++half) {
            const int r = mbase + mi * 16 + qrow + half * 8;
            const int m = m0 + r;
            const int bb = m >> 11;
            const int ss = m & (SLEN - 1);
#pragma unroll
            for (int nj = 0; nj < 4; ++nj) {
                const int col = nbase + nj * 8 + qcol;
                const float v0 = acc[mi][nj][half * 2];
                const float v1 = acc[mi][nj][half * 2 + 1];
                if (IS_O) {
                    float2 vv; vv.x = v0; vv.y = v1;
                    *(float2*)(out + (size_t)m * HID + nb * 128 + col) = vv;
                } else if (nb < 7) {
                    const int gc = nb * 128 + col;
                    const int h = gc >> 6, d0 = gc & 63;
                    float2 vv;
                    vv.x = v0 + bq[gc];
                    vv.y = v1 + bq[gc + 1];
                    *(float2*)(g_Q + (((size_t)(bb * NH + h)) * SLEN + ss) * HD + d0) = vv;
                } else if (nb == 7) {
                    const int h = col >> 6, d0 = col & 63;
                    float2 vv;
                    vv.x = v0 + bk[col];
                    vv.y = v1 + bk[col + 1];
                    *(float2*)(g_K + (((size_t)(bb * NKV + h)) * SLEN + ss) * HD + d0) = vv;
                } else {
                    const int h = col >> 6, d0 = col & 63;
                    const size_t off = (((size_t)(bb * NKV + h)) * SLEN + ss) * HD + d0;
                    *(u32*)(g_Vh + off) = pack2h(v0 + bv[col], v1 + bv[col + 1]);
                }
            }
        }
    }
}

// ---------------- RoPE: fp32 in; Q -> fp16 (x0.125), K -> fp16 ----------------
__global__ void rope_split_kernel(const int* __restrict__ pos_ids) {
    const int QROWS = BATCH * NH * SLEN;
    const int idx  = blockIdx.x * blockDim.x + threadIdx.x;
    const int pair = idx & 31;
    const int row  = idx >> 5;

    const int s = row & (SLEN - 1);
    const float p = (float)pos_ids[s];
    const float ang = p * g_invf[pair];
    float sn, cs;
    sincosf(ang, &sn, &cs);

    if (row < QROWS) {
        const float* base = g_Q + (size_t)row * HD;
        const float x1 = base[pair];
        const float x2 = base[pair + 32];
        const float y1 = (x1 * cs - x2 * sn) * 0.125f;
        const float y2 = (x2 * cs + x1 * sn) * 0.125f;
        u16* oh = g_Qh + (size_t)row * HD;
        __half h1 = __float2half_rn(y1);
        __half h2 = __float2half_rn(y2);
        oh[pair]      = *(u16*)&h1;
        oh[pair + 32] = *(u16*)&h2;
    } else {
        const int r2 = row - QROWS;
        const float* base = g_K + (size_t)r2 * HD;
        const float x1 = base[pair];
        const float x2 = base[pair + 32];
        const float y1 = x1 * cs - x2 * sn;
        const float y2 = x2 * cs + x1 * sn;
        u16* oh = g_Kh + (size_t)r2 * HD;
        __half h1 = __float2half_rn(y1);
        __half h2 = __float2half_rn(y2);
        oh[pair]      = *(u16*)&h1;
        oh[pair + 32] = *(u16*)&h2;
    }
}

// ---------------- Flash attention: single-term fp16, BM=128, BN=128 ----------------
#define F_STAGE 36864
#define F_SMEM  (2 * F_STAGE)

__global__ __launch_bounds__(256, 1)
void flash_mma() {
    extern __shared__ char smraw[];
    const u32 smb = smem_u32(smraw);
    const int tid  = threadIdx.x;
    const int wid  = tid >> 5;
    const int lane = tid & 31;

    const int blk = (int)gridDim.x - 1 - (int)blockIdx.x;
    const int h   = blockIdx.y;
    const int b   = blockIdx.z;
    const int qi0 = blk * 128;
    const int kh  = h / NREP;

    const u16* Qh = g_Qh + ((size_t)(b * NH + h)) * SLEN * HD;
    const size_t kvoff = ((size_t)(b * NKV + kh)) * SLEN * HD;
    const u16* Kh = g_Kh + kvoff;
    const u16* Vh = g_Vh + kvoff;

    const int qr = lane >> 2;
    const int q2 = (lane & 3) * 2;
    const int row0 = qi0 + wid * 16 + qr;

    auto issue = [&](int jt, int s) {
        const u32 sb = smb + (u32)s * F_STAGE;
        const int k0 = jt * 128;
#pragma unroll
        for (int buf = 0; buf < 2; ++buf) {
            const u16* src = buf ? Vh : Kh;
#pragma unroll
            for (int t = 0; t < 4; ++t) {
                const int cc  = tid + t * 256;
                const int row = cc >> 3;
                const int col = cc & 7;
                cp16(sb + buf * 18432 + row * 144 + col * 16,
                     src + (size_t)(k0 + row) * HD + col * 8);
            }
        }
    };

    issue(0, 0);
    CP_COMMIT();

    u32 qhi[4][4];
#pragma unroll
    for (int kk = 0; kk < 4; ++kk) {
#pragma unroll
        for (int part = 0; part < 4; ++part) {
            const int r = row0 + (part & 1) * 8;
            const int c = kk * 16 + q2 + (part & 2) * 4;
            qhi[kk][part] = *(const u32*)(Qh + (size_t)r * HD + c);
        }
    }

    float o[8][4];
#pragma unroll
    for (int i = 0; i < 8; ++i)
#pragma unroll
        for (int c = 0; c < 4; ++c) o[i][c] = 0.0f;
    float mx[2] = {-1e30f, -1e30f};
    float l[2]  = {0.0f, 0.0f};

    const int l7 = lane & 7;
    const int n_add = l7 + ((lane >> 4) & 1) * 8;
    const int k_add = ((lane >> 3) & 1) * 8;
    const int kv_add = l7 + ((lane >> 3) & 1) * 8;
    const int dv_add = ((lane >> 4) & 1) * 8;

    for (int j = 0; j <= blk; ++j) {
        const int k0 = j * 128;
        if (j < blk) issue(j + 1, (j + 1) & 1);
        CP_COMMIT();
        CP_WAIT1();
        __syncthreads();

        const u32 stg = smb + (u32)(j & 1) * F_STAGE;

        // ---- S = Q*K^T ----
        float sacc[16][4];
#pragma unroll
        for (int i = 0; i < 16; ++i)
#pragma unroll
            for (int c = 0; c < 4; ++c) sacc[i][c] = 0.0f;

#pragma unroll
        for (int kk = 0; kk < 4; ++kk) {
#pragma unroll
            for (int nbp = 0; nbp < 8; ++nbp) {
                const u32 ad = stg + (u32)((nbp * 16 + n_add) * 72 + k_add) * 2 + kk * 32;
                u32 kh4[4];
                ldsm4(kh4, ad);
                mma16816h(sacc[2 * nbp],     qhi[kk], &kh4[0]);
                mma16816h(sacc[2 * nbp + 1], qhi[kk], &kh4[2]);
            }
        }

        // ---- causal mask ----
        if (j == blk) {
#pragma unroll
            for (int nb = 0; nb < 16; ++nb) {
                const int colb = k0 + nb * 8 + q2;
#pragma unroll
                for (int c = 0; c < 4; ++c) {
                    const int col = colb + (c & 1);
                    const int row = row0 + (c >> 1) * 8;
                    if (col > row) sacc[nb][c] = -1e30f;
                }
            }
        }

        // ---- online softmax ----
#pragma unroll
        for (int hh = 0; hh < 2; ++hh) {
            float rm = -1e30f;
#pragma unroll
            for (int nb = 0; nb < 16; ++nb)
                rm = fmaxf(rm, fmaxf(sacc[nb][2 * hh], sacc[nb][2 * hh + 1]));
            rm = fmaxf(rm, __shfl_xor_sync(0xffffffffu, rm, 1));
            rm = fmaxf(rm, __shfl_xor_sync(0xffffffffu, rm, 2));

            const float mnew = fmaxf(mx[hh], rm);
            const float corr = __expf(mx[hh] - mnew);
            mx[hh] = mnew;

            float rs = 0.0f;
#pragma unroll
            for (int nb = 0; nb < 16; ++nb) {
                float p0 = __expf(sacc[nb][2 * hh] - mnew);
                float p1 = __expf(sacc[nb][2 * hh + 1] - mnew);
                sacc[nb][2 * hh] = p0;
                sacc[nb][2 * hh + 1] = p1;
                rs += p0 + p1;
            }
            rs += __shfl_xor_sync(0xffffffffu, rs, 1);
            rs += __shfl_xor_sync(0xffffffffu, rs, 2);
            l[hh] = l[hh] * corr + rs;
#pragma unroll
            for (int db = 0; db < 8; ++db) {
                o[db][2 * hh]     *= corr;
                o[db][2 * hh + 1] *= corr;
            }
        }

        // ---- pack P ----
        u32 phi[8][4];
#pragma unroll
        for (int kk = 0; kk < 8; ++kk) {
            phi[kk][0] = pack2h(sacc[2 * kk][0],     sacc[2 * kk][1]);
            phi[kk][1] = pack2h(sacc[2 * kk][2],     sacc[2 * kk][3]);
            phi[kk][2] = pack2h(sacc[2 * kk + 1][0], sacc[2 * kk + 1][1]);
            phi[kk][3] = pack2h(sacc[2 * kk + 1][2], sacc[2 * kk + 1][3]);
        }

        // ---- O += P*V ----
#pragma unroll
        for (int kk = 0; kk < 8; ++kk) {
#pragma unroll
            for (int dbp = 0; dbp < 4; ++dbp) {
                const u32 ad = stg + 18432 + (u32)((kk * 16 + kv_add) * 72 + dbp * 16 + dv_add) * 2;
                u32 vh4[4];
                ldsm4t(vh4, ad);
                mma16816h(o[2 * dbp],     phi[kk], &vh4[0]);
                mma16816h(o[2 * dbp + 1], phi[kk], &vh4[2]);
            }
        }
        __syncthreads();
    }

    // ---- epilogue: fp16 attn output ----
#pragma unroll
    for (int hh = 0; hh < 2; ++hh) {
        const float inv = 1.0f / l[hh];
        const int row = row0 + hh * 8;
        const size_t rb = ((size_t)(b * SLEN) + row) * (NH * HD) + h * HD;
#pragma unroll
        for (int db = 0; db < 8; ++db) {
            *(u32*)(g_Oh + rb + db * 8 + q2) =
                pack2h(o[db][2 * hh] * inv, o[db][2 * hh + 1] * inv);
        }
    }
}

// ---------------- launch ----------------
extern "C" void kernel_launch(void* const* d_in, const int* in_sizes, int n_in,
                              void* d_out, int out_size) {
    const float* hs  = (const float*)d_in[0];
    const int*   pos = (const int*)d_in[1];
    const float* Wq  = (const float*)d_in[2];
    const float* bq  = (const float*)d_in[3];
    const float* Wk  = (const float*)d_in[4];
    const float* bk  = (const float*)d_in[5];
    const float* Wv  = (const float*)d_in[6];
    const float* bv  = (const float*)d_in[7];
    const float* Wo  = (const float*)d_in[8];
    float* out = (float*)d_out;

    (void)in_sizes; (void)n_in; (void)out_size;

    cudaFuncSetAttribute(tc_gemm<0>, cudaFuncAttributeMaxDynamicSharedMemorySize, G_SMEM);
    cudaFuncSetAttribute(tc_gemm<1>, cudaFuncAttributeMaxDynamicSharedMemorySize, G_SMEM);
    cudaFuncSetAttribute(flash_mma, cudaFuncAttributeMaxDynamicSharedMemorySize, F_SMEM);

    init_invf_kernel<<<1, 32>>>();

    convert_kernel<<<(NA + NW) / 4 / 256, 256>>>(hs, Wq, Wk, Wv, Wo);

    // fused QKV projection: nb 0..6 Q, 7 K, 8 V
    tc_gemm<0><<<dim3(9, 64), 256, G_SMEM>>>(bq, bk, bv, nullptr);

    {
        const int qrows = BATCH * NH * SLEN;
        const int krows = BATCH * NKV * SLEN;
        const int total = (qrows + krows) * (HD / 2);
        rope_split_kernel<<<total / 256, 256>>>(pos);
    }

    flash_mma<<<dim3(SLEN / 128, NH, BATCH), 256, F_SMEM>>>();

    // O projection -> d_out
    tc_gemm<1><<<dim3(7, 64), 256, G_SMEM>>>(nullptr, nullptr, nullptr, out);
}

// round 15
// speedup vs baseline: 2.1715x; 1.0450x over previous
#include <cuda_runtime.h>
#include <cuda_bf16.h>
#include <cuda_fp16.h>
#include <math.h>

#define BATCH 4
#define SLEN  2048
#define HID   896
#define NH    14
#define NKV   2
#define HD    64
#define NREP  (NH / NKV)

typedef unsigned long long u64;
typedef unsigned int u32;
typedef unsigned short u16;

#define NA (8192 * 896)
#define NW (2048 * 896)
#define NQE (BATCH * NH * SLEN * HD)
#define NKE (BATCH * NKV * SLEN * HD)

// ---------------- scratch ----------------
__device__ float g_Q[NQE];              // fp32 post-GEMM Q (rope input)
__device__ float g_K[NKE];              // fp32 post-GEMM K (rope input)
__device__ u16 g_Ah[NA];                // hidden fp16
__device__ u16 g_Wh[NW];                // weights fp16
__device__ u16 g_Qh[NQE];               // roped Q*0.125*log2e, fp16
__device__ u16 g_Kh[NKE];               // roped K, fp16
__device__ u16 g_Vh[NKE];               // V, fp16
__device__ u16 g_Oh[NA];                // attn out fp16 (O-proj A operand)
__device__ float g_invf[HD / 2];

__global__ void init_invf_kernel() {
    int i = threadIdx.x;
    if (i < HD / 2) g_invf[i] = (float)pow(1.0e6, -(double)i / 32.0);
}

// ================= helpers =================
__device__ __forceinline__ u32 smem_u32(const void* p) {
    u32 a;
    asm("{ .reg .u64 t; cvta.to.shared.u64 t, %1; cvt.u32.u64 %0, t; }" : "=r"(a) : "l"(p));
    return a;
}
__device__ __forceinline__ void mma16816h(float* d, const u32* a, const u32* b) {
    asm volatile(
        "mma.sync.aligned.m16n8k16.row.col.f32.f16.f16.f32 "
        "{%0,%1,%2,%3}, {%4,%5,%6,%7}, {%8,%9}, {%0,%1,%2,%3};"
        : "+f"(d[0]), "+f"(d[1]), "+f"(d[2]), "+f"(d[3])
        : "r"(a[0]), "r"(a[1]), "r"(a[2]), "r"(a[3]), "r"(b[0]), "r"(b[1]));
}
__device__ __forceinline__ void ldsm4(u32* r, u32 addr) {
    asm volatile("ldmatrix.sync.aligned.m8n8.x4.shared.b16 {%0,%1,%2,%3}, [%4];"
                 : "=r"(r[0]), "=r"(r[1]), "=r"(r[2]), "=r"(r[3]) : "r"(addr));
}
__device__ __forceinline__ void ldsm4t(u32* r, u32 addr) {
    asm volatile("ldmatrix.sync.aligned.m8n8.x4.trans.shared.b16 {%0,%1,%2,%3}, [%4];"
                 : "=r"(r[0]), "=r"(r[1]), "=r"(r[2]), "=r"(r[3]) : "r"(addr));
}
__device__ __forceinline__ u32 pack2h(float x, float y) {
    __half2 h = __floats2half2_rn(x, y);
    return *(u32*)&h;
}
// 2^x on a packed pair, fp16 approx (x low, y high)
__device__ __forceinline__ u32 ex2h2(float x, float y) {
    u32 h, r;
    asm("cvt.rn.f16x2.f32 %0, %1, %2;" : "=r"(h) : "f"(y), "f"(x));
    asm("ex2.approx.f16x2 %0, %1;" : "=r"(r) : "r"(h));
    return r;
}
__device__ __forceinline__ float ex2f(float x) {
    float r;
    asm("ex2.approx.f32 %0, %1;" : "=f"(r) : "f"(x));
    return r;
}
__device__ __forceinline__ void cp16(u32 smem, const void* g) {
    asm volatile("cp.async.cg.shared.global [%0], [%1], 16;" :: "r"(smem), "l"(g));
}
#define CP_COMMIT() asm volatile("cp.async.commit_group;" ::: "memory")
#define CP_WAIT1()  asm volatile("cp.async.wait_group 1;" ::: "memory")

// ---------------- one-shot fp32 -> fp16 conversion ----------------
__global__ void convert_kernel(const float* __restrict__ hs,
                               const float* __restrict__ Wq, const float* __restrict__ Wk,
                               const float* __restrict__ Wv, const float* __restrict__ Wo) {
    const int idx = blockIdx.x * blockDim.x + threadIdx.x;
    const size_t f4 = (size_t)idx * 4;
    if (f4 < NA) {
        float4 v = *(const float4*)(hs + f4);
        *(uint2*)(g_Ah + f4) = make_uint2(pack2h(v.x, v.y), pack2h(v.z, v.w));
    } else {
        const size_t g = f4 - NA;
        if (g >= NW) return;
        const int row = (int)(g / 896);
        const float* src;
        if (row < 896)       src = Wq + g;
        else if (row < 1024) src = Wk + (g - (size_t)896 * 896);
        else if (row < 1152) src = Wv + (g - (size_t)1024 * 896);
        else                 src = Wo + (g - (size_t)1152 * 896);
        float4 v = *(const float4*)src;
        *(uint2*)(g_Wh + g) = make_uint2(pack2h(v.x, v.y), pack2h(v.z, v.w));
    }
}

// ============ GEMM: 128x128 tile, 8 warps (2m x 4n), single-term fp16 ============
#define G_STAGE 36864
#define G_SMEM  (2 * G_STAGE)

template <int IS_O>
__global__ __launch_bounds__(256, 1)
void tc_gemm(const float* __restrict__ bq, const float* __restrict__ bk,
             const float* __restrict__ bv, float* __restrict__ out)
{
    extern __shared__ char smraw[];
    const u32 smb = smem_u32(smraw);
    const int tid  = threadIdx.x;
    const int wid  = tid >> 5;
    const int lane = tid & 31;
    const int nb   = blockIdx.x;
    const int m0   = blockIdx.y * 128;

    const int wrow0 = IS_O ? (1152 + nb * 128) : (nb * 128);
    const u16* pAh = (IS_O ? g_Oh : g_Ah) + (size_t)m0 * 896;
    const u16* pBh = g_Wh + (size_t)wrow0 * 896;

    const int mbase = (wid & 1) * 64;
    const int nbase = (wid >> 1) * 32;

    const int g  = lane >> 3;
    const int l7 = lane & 7;
    const u32 aoffB = (u32)((mbase + (g & 1) * 8 + l7) * 72 + (g >> 1) * 8) * 2;
    const u32 boffB = (u32)((nbase + (g >> 1) * 8 + l7) * 72 + (g & 1) * 8) * 2;

    float acc[4][4][4];
#pragma unroll
    for (int i = 0; i < 4; ++i)
#pragma unroll
        for (int j = 0; j < 4; ++j)
#pragma unroll
            for (int k = 0; k < 4; ++k) acc[i][j][k] = 0.0f;

    auto issue = [&](int chunk, int s) {
        const u32 sb = smb + (u32)s * G_STAGE;
        const int kc0 = chunk * 64;
#pragma unroll
        for (int buf = 0; buf < 2; ++buf) {
            const u16* src = buf ? pBh : pAh;
#pragma unroll
            for (int t = 0; t < 4; ++t) {
                const int cc  = tid + t * 256;
                const int row = cc >> 3;
                const int col = cc & 7;
                cp16(sb + buf * 18432 + row * 144 + col * 16,
                     src + (size_t)row * 896 + kc0 + col * 8);
            }
        }
    };

    issue(0, 0);
    CP_COMMIT();

    for (int it = 0; it < 14; ++it) {
        if (it + 1 < 14) issue(it + 1, (it + 1) & 1);
        CP_COMMIT();
        CP_WAIT1();
        __syncthreads();

        const u32 stg = smb + (u32)(it & 1) * G_STAGE;
#pragma unroll
        for (int ks = 0; ks < 4; ++ks) {
            u32 ahi[4][4];
#pragma unroll
            for (int mi = 0; mi < 4; ++mi) {
                const u32 ad = stg + aoffB + (u32)(mi * 16 * 72) * 2 + ks * 32;
                ldsm4(ahi[mi], ad);
            }
            u32 bhi[4][2];
#pragma unroll
            for (int jp = 0; jp < 2; ++jp) {
                const u32 bd = stg + 18432 + boffB + (u32)(jp * 16 * 72) * 2 + ks * 32;
                u32 t4[4];
                ldsm4(t4, bd);
                bhi[2 * jp][0] = t4[0]; bhi[2 * jp][1] = t4[1];
                bhi[2 * jp + 1][0] = t4[2]; bhi[2 * jp + 1][1] = t4[3];
            }
#pragma unroll
            for (int mi = 0; mi < 4; ++mi)
#pragma unroll
                for (int nj = 0; nj < 4; ++nj)
                    mma16816h(acc[mi][nj], ahi[mi], bhi[nj]);
        }
        __syncthreads();
    }

    const int qrow = lane >> 2;
    const int qcol = (lane & 3) * 2;
#pragma unroll
    for (int mi = 0; mi < 4; ++mi) {
#pragma unroll
        for (int half = 0; half < 2; ++half) {
            const int r = mbase + mi * 16 + qrow + half * 8;
            const int m = m0 + r;
            const int bb = m >> 11;
            const int ss = m & (SLEN - 1);
#pragma unroll
            for (int nj = 0; nj < 4; ++nj) {
                const int col = nbase + nj * 8 + qcol;
                const float v0 = acc[mi][nj][half * 2];
                const float v1 = acc[mi][nj][half * 2 + 1];
                if (IS_O) {
                    float2 vv; vv.x = v0; vv.y = v1;
                    *(float2*)(out + (size_t)m * HID + nb * 128 + col) = vv;
                } else if (nb < 7) {
                    const int gc = nb * 128 + col;
                    const int h = gc >> 6, d0 = gc & 63;
                    float2 vv;
                    vv.x = v0 + bq[gc];
                    vv.y = v1 + bq[gc + 1];
                    *(float2*)(g_Q + (((size_t)(bb * NH + h)) * SLEN + ss) * HD + d0) = vv;
                } else if (nb == 7) {
                    const int h = col >> 6, d0 = col & 63;
                    float2 vv;
                    vv.x = v0 + bk[col];
                    vv.y = v1 + bk[col + 1];
                    *(float2*)(g_K + (((size_t)(bb * NKV + h)) * SLEN + ss) * HD + d0) = vv;
                } else {
                    const int h = col >> 6, d0 = col & 63;
                    const size_t off = (((size_t)(bb * NKV + h)) * SLEN + ss) * HD + d0;
                    *(u32*)(g_Vh + off) = pack2h(v0 + bv[col], v1 + bv[col + 1]);
                }
            }
        }
    }
}

// ---------------- RoPE: fp32 in; Q -> fp16 (x 0.125*log2e), K -> fp16 ----------------
#define QSCALE 0.18033688011112042f   // 0.125 * log2(e)

__global__ void rope_split_kernel(const int* __restrict__ pos_ids) {
    const int QROWS = BATCH * NH * SLEN;
    const int idx  = blockIdx.x * blockDim.x + threadIdx.x;
    const int pair = idx & 31;
    const int row  = idx >> 5;

    const int s = row & (SLEN - 1);
    const float p = (float)pos_ids[s];
    const float ang = p * g_invf[pair];
    float sn, cs;
    sincosf(ang, &sn, &cs);

    if (row < QROWS) {
        const float* base = g_Q + (size_t)row * HD;
        const float x1 = base[pair];
        const float x2 = base[pair + 32];
        const float y1 = (x1 * cs - x2 * sn) * QSCALE;
        const float y2 = (x2 * cs + x1 * sn) * QSCALE;
        u16* oh = g_Qh + (size_t)row * HD;
        __half h1 = __float2half_rn(y1);
        __half h2 = __float2half_rn(y2);
        oh[pair]      = *(u16*)&h1;
        oh[pair + 32] = *(u16*)&h2;
    } else {
        const int r2 = row - QROWS;
        const float* base = g_K + (size_t)r2 * HD;
        const float x1 = base[pair];
        const float x2 = base[pair + 32];
        const float y1 = x1 * cs - x2 * sn;
        const float y2 = x2 * cs + x1 * sn;
        u16* oh = g_Kh + (size_t)r2 * HD;
        __half h1 = __float2half_rn(y1);
        __half h2 = __float2half_rn(y2);
        oh[pair]      = *(u16*)&h1;
        oh[pair + 32] = *(u16*)&h2;
    }
}

// ---------------- Flash attention: fp16, exp2-domain softmax, l via P*ones MMA ----------------
#define F_STAGE 36864
#define F_SMEM  (2 * F_STAGE)

__global__ __launch_bounds__(256, 1)
void flash_mma() {
    extern __shared__ char smraw[];
    const u32 smb = smem_u32(smraw);
    const int tid  = threadIdx.x;
    const int wid  = tid >> 5;
    const int lane = tid & 31;

    const int blk = (int)gridDim.x - 1 - (int)blockIdx.x;
    const int h   = blockIdx.y;
    const int b   = blockIdx.z;
    const int qi0 = blk * 128;
    const int kh  = h / NREP;

    const u16* Qh = g_Qh + ((size_t)(b * NH + h)) * SLEN * HD;
    const size_t kvoff = ((size_t)(b * NKV + kh)) * SLEN * HD;
    const u16* Kh = g_Kh + kvoff;
    const u16* Vh = g_Vh + kvoff;

    const int qr = lane >> 2;
    const int q2 = (lane & 3) * 2;
    const int row0 = qi0 + wid * 16 + qr;

    auto issue = [&](int jt, int s) {
        const u32 sb = smb + (u32)s * F_STAGE;
        const int k0 = jt * 128;
#pragma unroll
        for (int buf = 0; buf < 2; ++buf) {
            const u16* src = buf ? Vh : Kh;
#pragma unroll
            for (int t = 0; t < 4; ++t) {
                const int cc  = tid + t * 256;
                const int row = cc >> 3;
                const int col = cc & 7;
                cp16(sb + buf * 18432 + row * 144 + col * 16,
                     src + (size_t)(k0 + row) * HD + col * 8);
            }
        }
    };

    issue(0, 0);
    CP_COMMIT();

    u32 qhi[4][4];
#pragma unroll
    for (int kk = 0; kk < 4; ++kk) {
#pragma unroll
        for (int part = 0; part < 4; ++part) {
            const int r = row0 + (part & 1) * 8;
            const int c = kk * 16 + q2 + (part & 2) * 4;
            qhi[kk][part] = *(const u32*)(Qh + (size_t)r * HD + c);
        }
    }

    float o[8][4];
#pragma unroll
    for (int i = 0; i < 8; ++i)
#pragma unroll
        for (int c = 0; c < 4; ++c) o[i][c] = 0.0f;
    float mx[2] = {-1e30f, -1e30f};
    float l[2]  = {0.0f, 0.0f};

    const u32 ones2[2] = {0x3C003C00u, 0x3C003C00u};

    const int l7 = lane & 7;
    const int n_add = l7 + ((lane >> 4) & 1) * 8;
    const int k_add = ((lane >> 3) & 1) * 8;
    const int kv_add = l7 + ((lane >> 3) & 1) * 8;
    const int dv_add = ((lane >> 4) & 1) * 8;

    for (int j = 0; j <= blk; ++j) {
        const int k0 = j * 128;
        if (j < blk) issue(j + 1, (j + 1) & 1);
        CP_COMMIT();
        CP_WAIT1();
        __syncthreads();

        const u32 stg = smb + (u32)(j & 1) * F_STAGE;

        // ---- S = Q*K^T (log2 domain) ----
        float sacc[16][4];
#pragma unroll
        for (int i = 0; i < 16; ++i)
#pragma unroll
            for (int c = 0; c < 4; ++c) sacc[i][c] = 0.0f;

#pragma unroll
        for (int kk = 0; kk < 4; ++kk) {
#pragma unroll
            for (int nbp = 0; nbp < 8; ++nbp) {
                const u32 ad = stg + (u32)((nbp * 16 + n_add) * 72 + k_add) * 2 + kk * 32;
                u32 kh4[4];
                ldsm4(kh4, ad);
                mma16816h(sacc[2 * nbp],     qhi[kk], &kh4[0]);
                mma16816h(sacc[2 * nbp + 1], qhi[kk], &kh4[2]);
            }
        }

        // ---- causal mask ----
        if (j == blk) {
#pragma unroll
            for (int nb = 0; nb < 16; ++nb) {
                const int colb = k0 + nb * 8 + q2;
#pragma unroll
                for (int c = 0; c < 4; ++c) {
                    const int col = colb + (c & 1);
                    const int row = row0 + (c >> 1) * 8;
                    if (col > row) sacc[nb][c] = -1e30f;
                }
            }
        }

        // ---- online softmax state (max + corr), per row-half ----
        float mnew[2], corr[2];
#pragma unroll
        for (int hh = 0; hh < 2; ++hh) {
            float rm = -1e30f;
#pragma unroll
            for (int nb = 0; nb < 16; ++nb)
                rm = fmaxf(rm, fmaxf(sacc[nb][2 * hh], sacc[nb][2 * hh + 1]));
            rm = fmaxf(rm, __shfl_xor_sync(0xffffffffu, rm, 1));
            rm = fmaxf(rm, __shfl_xor_sync(0xffffffffu, rm, 2));

            mnew[hh] = fmaxf(mx[hh], rm);
            corr[hh] = ex2f(mx[hh] - mnew[hh]);
            mx[hh] = mnew[hh];
#pragma unroll
            for (int db = 0; db < 8; ++db) {
                o[db][2 * hh]     *= corr[hh];
                o[db][2 * hh + 1] *= corr[hh];
            }
        }

        // ---- P = 2^(s - m), packed fp16 directly into A-fragments ----
        u32 phi[8][4];
#pragma unroll
        for (int kk = 0; kk < 8; ++kk) {
            phi[kk][0] = ex2h2(sacc[2 * kk][0] - mnew[0],     sacc[2 * kk][1] - mnew[0]);
            phi[kk][1] = ex2h2(sacc[2 * kk][2] - mnew[1],     sacc[2 * kk][3] - mnew[1]);
            phi[kk][2] = ex2h2(sacc[2 * kk + 1][0] - mnew[0], sacc[2 * kk + 1][1] - mnew[0]);
            phi[kk][3] = ex2h2(sacc[2 * kk + 1][2] - mnew[1], sacc[2 * kk + 1][3] - mnew[1]);
        }

        // ---- row sums via P x ones MMA (reduces over k across quad lanes) ----
        {
            float lacc[4] = {0.0f, 0.0f, 0.0f, 0.0f};
#pragma unroll
            for (int kk = 0; kk < 8; ++kk)
                mma16816h(lacc, phi[kk], ones2);
            l[0] = l[0] * corr[0] + lacc[0];
            l[1] = l[1] * corr[1] + lacc[2];
        }

        // ---- O += P*V ----
#pragma unroll
        for (int kk = 0; kk < 8; ++kk) {
#pragma unroll
            for (int dbp = 0; dbp < 4; ++dbp) {
                const u32 ad = stg + 18432 + (u32)((kk * 16 + kv_add) * 72 + dbp * 16 + dv_add) * 2;
                u32 vh4[4];
                ldsm4t(vh4, ad);
                mma16816h(o[2 * dbp],     phi[kk], &vh4[0]);
                mma16816h(o[2 * dbp + 1], phi[kk], &vh4[2]);
            }
        }
        __syncthreads();
    }

    // ---- epilogue: fp16 attn output ----
#pragma unroll
    for (int hh = 0; hh < 2; ++hh) {
        const float inv = 1.0f / l[hh];
        const int row = row0 + hh * 8;
        const size_t rb = ((size_t)(b * SLEN) + row) * (NH * HD) + h * HD;
#pragma unroll
        for (int db = 0; db < 8; ++db) {
            *(u32*)(g_Oh + rb + db * 8 + q2) =
                pack2h(o[db][2 * hh] * inv, o[db][2 * hh + 1] * inv);
        }
    }
}

// ---------------- launch ----------------
extern "C" void kernel_launch(void* const* d_in, const int* in_sizes, int n_in,
                              void* d_out, int out_size) {
    const float* hs  = (const float*)d_in[0];
    const int*   pos = (const int*)d_in[1];
    const float* Wq  = (const float*)d_in[2];
    const float* bq  = (const float*)d_in[3];
    const float* Wk  = (const float*)d_in[4];
    const float* bk  = (const float*)d_in[5];
    const float* Wv  = (const float*)d_in[6];
    const float* bv  = (const float*)d_in[7];
    const float* Wo  = (const float*)d_in[8];
    float* out = (float*)d_out;

    (void)in_sizes; (void)n_in; (void)out_size;

    cudaFuncSetAttribute(tc_gemm<0>, cudaFuncAttributeMaxDynamicSharedMemorySize, G_SMEM);
    cudaFuncSetAttribute(tc_gemm<1>, cudaFuncAttributeMaxDynamicSharedMemorySize, G_SMEM);
    cudaFuncSetAttribute(flash_mma, cudaFuncAttributeMaxDynamicSharedMemorySize, F_SMEM);

    init_invf_kernel<<<1, 32>>>();

    convert_kernel<<<(NA + NW) / 4 / 256, 256>>>(hs, Wq, Wk, Wv, Wo);

    // fused QKV projection: nb 0..6 Q, 7 K, 8 V
    tc_gemm<0><<<dim3(9, 64), 256, G_SMEM>>>(bq, bk, bv, nullptr);

    {
        const int qrows = BATCH * NH * SLEN;
        const int krows = BATCH * NKV * SLEN;
        const int total = (qrows + krows) * (HD / 2);
        rope_split_kernel<<<total / 256, 256>>>(pos);
    }

    flash_mma<<<dim3(SLEN / 128, NH, BATCH), 256, F_SMEM>>>();

    // O projection -> d_out
    tc_gemm<1><<<dim3(7, 64), 256, G_SMEM>>>(nullptr, nullptr, nullptr, out);
}

// round 16
// speedup vs baseline: 2.3952x; 1.1030x over previous
#include <cuda_runtime.h>
#include <cuda_bf16.h>
#include <cuda_fp16.h>
#include <math.h>

#define BATCH 4
#define SLEN  2048
#define HID   896
#define NH    14
#define NKV   2
#define HD    64
#define NREP  (NH / NKV)

typedef unsigned long long u64;
typedef unsigned int u32;
typedef unsigned short u16;

#define NA (8192 * 896)
#define NW (2048 * 896)
#define NQE (BATCH * NH * SLEN * HD)
#define NKE (BATCH * NKV * SLEN * HD)

// ---------------- scratch ----------------
__device__ float g_Q[NQE];              // fp32 post-GEMM Q (rope input)
__device__ float g_K[NKE];              // fp32 post-GEMM K (rope input)
__device__ u16 g_Ah[NA];                // hidden fp16
__device__ u16 g_Wh[NW];                // weights fp16
__device__ u16 g_Qh[NQE];               // roped Q*0.125*log2e, fp16
__device__ u16 g_Kh[NKE];               // roped K, fp16
__device__ u16 g_Vh[NKE];               // V, fp16
__device__ u16 g_Oh[NA];                // attn out fp16 (O-proj A operand)
__device__ float g_invf[HD / 2];

// ================= helpers =================
__device__ __forceinline__ u32 smem_u32(const void* p) {
    u32 a;
    asm("{ .reg .u64 t; cvta.to.shared.u64 t, %1; cvt.u32.u64 %0, t; }" : "=r"(a) : "l"(p));
    return a;
}
__device__ __forceinline__ void mma16816h(float* d, const u32* a, const u32* b) {
    asm volatile(
        "mma.sync.aligned.m16n8k16.row.col.f32.f16.f16.f32 "
        "{%0,%1,%2,%3}, {%4,%5,%6,%7}, {%8,%9}, {%0,%1,%2,%3};"
        : "+f"(d[0]), "+f"(d[1]), "+f"(d[2]), "+f"(d[3])
        : "r"(a[0]), "r"(a[1]), "r"(a[2]), "r"(a[3]), "r"(b[0]), "r"(b[1]));
}
__device__ __forceinline__ void ldsm4(u32* r, u32 addr) {
    asm volatile("ldmatrix.sync.aligned.m8n8.x4.shared.b16 {%0,%1,%2,%3}, [%4];"
                 : "=r"(r[0]), "=r"(r[1]), "=r"(r[2]), "=r"(r[3]) : "r"(addr));
}
__device__ __forceinline__ void ldsm4t(u32* r, u32 addr) {
    asm volatile("ldmatrix.sync.aligned.m8n8.x4.trans.shared.b16 {%0,%1,%2,%3}, [%4];"
                 : "=r"(r[0]), "=r"(r[1]), "=r"(r[2]), "=r"(r[3]) : "r"(addr));
}
__device__ __forceinline__ u32 pack2h(float x, float y) {
    __half2 h = __floats2half2_rn(x, y);
    return *(u32*)&h;
}
__device__ __forceinline__ u32 ex2h2(float x, float y) {
    u32 h, r;
    asm("cvt.rn.f16x2.f32 %0, %1, %2;" : "=r"(h) : "f"(y), "f"(x));
    asm("ex2.approx.f16x2 %0, %1;" : "=r"(r) : "r"(h));
    return r;
}
__device__ __forceinline__ float ex2f(float x) {
    float r;
    asm("ex2.approx.f32 %0, %1;" : "=f"(r) : "f"(x));
    return r;
}
__device__ __forceinline__ void cp16(u32 smem, const void* g) {
    asm volatile("cp.async.cg.shared.global [%0], [%1], 16;" :: "r"(smem), "l"(g));
}
#define CP_COMMIT() asm volatile("cp.async.commit_group;" ::: "memory")
#define CP_WAIT1()  asm volatile("cp.async.wait_group 1;" ::: "memory")

// ---------------- one-shot fp32 -> fp16 conversion (+ invf init in block 0) ----------------
__global__ void convert_kernel(const float* __restrict__ hs,
                               const float* __restrict__ Wq, const float* __restrict__ Wk,
                               const float* __restrict__ Wv, const float* __restrict__ Wo) {
    if (blockIdx.x == 0 && threadIdx.x < HD / 2) {
        g_invf[threadIdx.x] = (float)pow(1.0e6, -(double)threadIdx.x / 32.0);
    }
    const int idx = blockIdx.x * blockDim.x + threadIdx.x;
    const size_t f4 = (size_t)idx * 4;
    if (f4 < NA) {
        float4 v = *(const float4*)(hs + f4);
        *(uint2*)(g_Ah + f4) = make_uint2(pack2h(v.x, v.y), pack2h(v.z, v.w));
    } else {
        const size_t g = f4 - NA;
        if (g >= NW) return;
        const int row = (int)(g / 896);
        const float* src;
        if (row < 896)       src = Wq + g;
        else if (row < 1024) src = Wk + (g - (size_t)896 * 896);
        else if (row < 1152) src = Wv + (g - (size_t)1024 * 896);
        else                 src = Wo + (g - (size_t)1152 * 896);
        float4 v = *(const float4*)src;
        *(uint2*)(g_Wh + g) = make_uint2(pack2h(v.x, v.y), pack2h(v.z, v.w));
    }
}

// ============ GEMM: 128x128 tile, 8 warps (2m x 4n), single-term fp16, 2 CTAs/SM ============
#define G_STAGE 36864
#define G_SMEM  (2 * G_STAGE)

template <int IS_O>
__global__ __launch_bounds__(256, 2)
void tc_gemm(const float* __restrict__ bq, const float* __restrict__ bk,
             const float* __restrict__ bv, float* __restrict__ out)
{
    extern __shared__ char smraw[];
    const u32 smb = smem_u32(smraw);
    const int tid  = threadIdx.x;
    const int wid  = tid >> 5;
    const int lane = tid & 31;
    const int nb   = blockIdx.x;
    const int m0   = blockIdx.y * 128;

    const int wrow0 = IS_O ? (1152 + nb * 128) : (nb * 128);
    const u16* pAh = (IS_O ? g_Oh : g_Ah) + (size_t)m0 * 896;
    const u16* pBh = g_Wh + (size_t)wrow0 * 896;

    const int mbase = (wid & 1) * 64;
    const int nbase = (wid >> 1) * 32;

    const int g  = lane >> 3;
    const int l7 = lane & 7;
    const u32 aoffB = (u32)((mbase + (g & 1) * 8 + l7) * 72 + (g >> 1) * 8) * 2;
    const u32 boffB = (u32)((nbase + (g >> 1) * 8 + l7) * 72 + (g & 1) * 8) * 2;

    float acc[4][4][4];
#pragma unroll
    for (int i = 0; i < 4; ++i)
#pragma unroll
        for (int j = 0; j < 4; ++j)
#pragma unroll
            for (int k = 0; k < 4; ++k) acc[i][j][k] = 0.0f;

    auto issue = [&](int chunk, int s) {
        const u32 sb = smb + (u32)s * G_STAGE;
        const int kc0 = chunk * 64;
#pragma unroll
        for (int buf = 0; buf < 2; ++buf) {
            const u16* src = buf ? pBh : pAh;
#pragma unroll
            for (int t = 0; t < 4; ++t) {
                const int cc  = tid + t * 256;
                const int row = cc >> 3;
                const int col = cc & 7;
                cp16(sb + buf * 18432 + row * 144 + col * 16,
                     src + (size_t)row * 896 + kc0 + col * 8);
            }
        }
    };

    issue(0, 0);
    CP_COMMIT();

    for (int it = 0; it < 14; ++it) {
        if (it + 1 < 14) issue(it + 1, (it + 1) & 1);
        CP_COMMIT();
        CP_WAIT1();
        __syncthreads();

        const u32 stg = smb + (u32)(it & 1) * G_STAGE;
#pragma unroll
        for (int ks = 0; ks < 4; ++ks) {
            u32 ahi[4][4];
#pragma unroll
            for (int mi = 0; mi < 4; ++mi) {
                const u32 ad = stg + aoffB + (u32)(mi * 16 * 72) * 2 + ks * 32;
                ldsm4(ahi[mi], ad);
            }
            u32 bhi[4][2];
#pragma unroll
            for (int jp = 0; jp < 2; ++jp) {
                const u32 bd = stg + 18432 + boffB + (u32)(jp * 16 * 72) * 2 + ks * 32;
                u32 t4[4];
                ldsm4(t4, bd);
                bhi[2 * jp][0] = t4[0]; bhi[2 * jp][1] = t4[1];
                bhi[2 * jp + 1][0] = t4[2]; bhi[2 * jp + 1][1] = t4[3];
            }
#pragma unroll
            for (int mi = 0; mi < 4; ++mi)
#pragma unroll
                for (int nj = 0; nj < 4; ++nj)
                    mma16816h(acc[mi][nj], ahi[mi], bhi[nj]);
        }
        __syncthreads();
    }

    const int qrow = lane >> 2;
    const int qcol = (lane & 3) * 2;
#pragma unroll
    for (int mi = 0; mi < 4; ++mi) {
#pragma unroll
        for (int half = 0; half < 2; ++half) {
            const int r = mbase + mi * 16 + qrow + half * 8;
            const int m = m0 + r;
            const int bb = m >> 11;
            const int ss = m & (SLEN - 1);
#pragma unroll
            for (int nj = 0; nj < 4; ++nj) {
                const int col = nbase + nj * 8 + qcol;
                const float v0 = acc[mi][nj][half * 2];
                const float v1 = acc[mi][nj][half * 2 + 1];
                if (IS_O) {
                    float2 vv; vv.x = v0; vv.y = v1;
                    *(float2*)(out + (size_t)m * HID + nb * 128 + col) = vv;
                } else if (nb < 7) {
                    const int gc = nb * 128 + col;
                    const int h = gc >> 6, d0 = gc & 63;
                    float2 vv;
                    vv.x = v0 + bq[gc];
                    vv.y = v1 + bq[gc + 1];
                    *(float2*)(g_Q + (((size_t)(bb * NH + h)) * SLEN + ss) * HD + d0) = vv;
                } else if (nb == 7) {
                    const int h = col >> 6, d0 = col & 63;
                    float2 vv;
                    vv.x = v0 + bk[col];
                    vv.y = v1 + bk[col + 1];
                    *(float2*)(g_K + (((size_t)(bb * NKV + h)) * SLEN + ss) * HD + d0) = vv;
                } else {
                    const int h = col >> 6, d0 = col & 63;
                    const size_t off = (((size_t)(bb * NKV + h)) * SLEN + ss) * HD + d0;
                    *(u32*)(g_Vh + off) = pack2h(v0 + bv[col], v1 + bv[col + 1]);
                }
            }
        }
    }
}

// ---------------- RoPE: fp32 in; Q -> fp16 (x 0.125*log2e), K -> fp16 ----------------
#define QSCALE 0.18033688011112042f   // 0.125 * log2(e)

__global__ void rope_split_kernel(const int* __restrict__ pos_ids) {
    const int QROWS = BATCH * NH * SLEN;
    const int idx  = blockIdx.x * blockDim.x + threadIdx.x;
    const int pair = idx & 31;
    const int row  = idx >> 5;

    const int s = row & (SLEN - 1);
    const float p = (float)pos_ids[s];
    const float ang = p * g_invf[pair];
    float sn, cs;
    sincosf(ang, &sn, &cs);

    if (row < QROWS) {
        const float* base = g_Q + (size_t)row * HD;
        const float x1 = base[pair];
        const float x2 = base[pair + 32];
        const float y1 = (x1 * cs - x2 * sn) * QSCALE;
        const float y2 = (x2 * cs + x1 * sn) * QSCALE;
        u16* oh = g_Qh + (size_t)row * HD;
        __half h1 = __float2half_rn(y1);
        __half h2 = __float2half_rn(y2);
        oh[pair]      = *(u16*)&h1;
        oh[pair + 32] = *(u16*)&h2;
    } else {
        const int r2 = row - QROWS;
        const float* base = g_K + (size_t)r2 * HD;
        const float x1 = base[pair];
        const float x2 = base[pair + 32];
        const float y1 = x1 * cs - x2 * sn;
        const float y2 = x2 * cs + x1 * sn;
        u16* oh = g_Kh + (size_t)r2 * HD;
        __half h1 = __float2half_rn(y1);
        __half h2 = __float2half_rn(y2);
        oh[pair]      = *(u16*)&h1;
        oh[pair + 32] = *(u16*)&h2;
    }
}

// ---------------- Flash attention: fp16, exp2-domain softmax, l via P*ones MMA ----------------
#define F_STAGE 36864
#define F_SMEM  (2 * F_STAGE)

__global__ __launch_bounds__(256, 1)
void flash_mma() {
    extern __shared__ char smraw[];
    const u32 smb = smem_u32(smraw);
    const int tid  = threadIdx.x;
    const int wid  = tid >> 5;
    const int lane = tid & 31;

    const int blk = (int)gridDim.x - 1 - (int)blockIdx.x;
    const int h   = blockIdx.y;
    const int b   = blockIdx.z;
    const int qi0 = blk * 128;
    const int kh  = h / NREP;

    const u16* Qh = g_Qh + ((size_t)(b * NH + h)) * SLEN * HD;
    const size_t kvoff = ((size_t)(b * NKV + kh)) * SLEN * HD;
    const u16* Kh = g_Kh + kvoff;
    const u16* Vh = g_Vh + kvoff;

    const int qr = lane >> 2;
    const int q2 = (lane & 3) * 2;
    const int row0 = qi0 + wid * 16 + qr;

    auto issue = [&](int jt, int s) {
        const u32 sb = smb + (u32)s * F_STAGE;
        const int k0 = jt * 128;
#pragma unroll
        for (int buf = 0; buf < 2; ++buf) {
            const u16* src = buf ? Vh : Kh;
#pragma unroll
            for (int t = 0; t < 4; ++t) {
                const int cc  = tid + t * 256;
                const int row = cc >> 3;
                const int col = cc & 7;
                cp16(sb + buf * 18432 + row * 144 + col * 16,
                     src + (size_t)(k0 + row) * HD + col * 8);
            }
        }
    };

    issue(0, 0);
    CP_COMMIT();

    u32 qhi[4][4];
#pragma unroll
    for (int kk = 0; kk < 4; ++kk) {
#pragma unroll
        for (int part = 0; part < 4; ++part) {
            const int r = row0 + (part & 1) * 8;
            const int c = kk * 16 + q2 + (part & 2) * 4;
            qhi[kk][part] = *(const u32*)(Qh + (size_t)r * HD + c);
        }
    }

    float o[8][4];
#pragma unroll
    for (int i = 0; i < 8; ++i)
#pragma unroll
        for (int c = 0; c < 4; ++c) o[i][c] = 0.0f;
    float mx[2] = {-1e30f, -1e30f};
    float l[2]  = {0.0f, 0.0f};

    const u32 ones2[2] = {0x3C003C00u, 0x3C003C00u};

    const int l7 = lane & 7;
    const int n_add = l7 + ((lane >> 4) & 1) * 8;
    const int k_add = ((lane >> 3) & 1) * 8;
    const int kv_add = l7 + ((lane >> 3) & 1) * 8;
    const int dv_add = ((lane >> 4) & 1) * 8;

    for (int j = 0; j <= blk; ++j) {
        const int k0 = j * 128;
        if (j < blk) issue(j + 1, (j + 1) & 1);
        CP_COMMIT();
        CP_WAIT1();
        __syncthreads();

        const u32 stg = smb + (u32)(j & 1) * F_STAGE;

        // ---- S = Q*K^T (log2 domain) ----
        float sacc[16][4];
#pragma unroll
        for (int i = 0; i < 16; ++i)
#pragma unroll
            for (int c = 0; c < 4; ++c) sacc[i][c] = 0.0f;

#pragma unroll
        for (int kk = 0; kk < 4; ++kk) {
#pragma unroll
            for (int nbp = 0; nbp < 8; ++nbp) {
                const u32 ad = stg + (u32)((nbp * 16 + n_add) * 72 + k_add) * 2 + kk * 32;
                u32 kh4[4];
                ldsm4(kh4, ad);
                mma16816h(sacc[2 * nbp],     qhi[kk], &kh4[0]);
                mma16816h(sacc[2 * nbp + 1], qhi[kk], &kh4[2]);
            }
        }

        // ---- causal mask ----
        if (j == blk) {
#pragma unroll
            for (int nb = 0; nb < 16; ++nb) {
                const int colb = k0 + nb * 8 + q2;
#pragma unroll
                for (int c = 0; c < 4; ++c) {
                    const int col = colb + (c & 1);
                    const int row = row0 + (c >> 1) * 8;
                    if (col > row) sacc[nb][c] = -1e30f;
                }
            }
        }

        // ---- online softmax state (max + corr), per row-half ----
        float mnew[2], corr[2];
#pragma unroll
        for (int hh = 0; hh < 2; ++hh) {
            float rm = -1e30f;
#pragma unroll
            for (int nb = 0; nb < 16; ++nb)
                rm = fmaxf(rm, fmaxf(sacc[nb][2 * hh], sacc[nb][2 * hh + 1]));
            rm = fmaxf(rm, __shfl_xor_sync(0xffffffffu, rm, 1));
            rm = fmaxf(rm, __shfl_xor_sync(0xffffffffu, rm, 2));

            mnew[hh] = fmaxf(mx[hh], rm);
            corr[hh] = ex2f(mx[hh] - mnew[hh]);
            mx[hh] = mnew[hh];
#pragma unroll
            for (int db = 0; db < 8; ++db) {
                o[db][2 * hh]     *= corr[hh];
                o[db][2 * hh + 1] *= corr[hh];
            }
        }

        // ---- P = 2^(s - m), packed fp16 directly into A-fragments ----
        u32 phi[8][4];
#pragma unroll
        for (int kk = 0; kk < 8; ++kk) {
            phi[kk][0] = ex2h2(sacc[2 * kk][0] - mnew[0],     sacc[2 * kk][1] - mnew[0]);
            phi[kk][1] = ex2h2(sacc[2 * kk][2] - mnew[1],     sacc[2 * kk][3] - mnew[1]);
            phi[kk][2] = ex2h2(sacc[2 * kk + 1][0] - mnew[0], sacc[2 * kk + 1][1] - mnew[0]);
            phi[kk][3] = ex2h2(sacc[2 * kk + 1][2] - mnew[1], sacc[2 * kk + 1][3] - mnew[1]);
        }

        // ---- row sums via P x ones MMA ----
        {
            float lacc[4] = {0.0f, 0.0f, 0.0f, 0.0f};
#pragma unroll
            for (int kk = 0; kk < 8; ++kk)
                mma16816h(lacc, phi[kk], ones2);
            l[0] = l[0] * corr[0] + lacc[0];
            l[1] = l[1] * corr[1] + lacc[2];
        }

        // ---- O += P*V ----
#pragma unroll
        for (int kk = 0; kk < 8; ++kk) {
#pragma unroll
            for (int dbp = 0; dbp < 4; ++dbp) {
                const u32 ad = stg + 18432 + (u32)((kk * 16 + kv_add) * 72 + dbp * 16 + dv_add) * 2;
                u32 vh4[4];
                ldsm4t(vh4, ad);
                mma16816h(o[2 * dbp],     phi[kk], &vh4[0]);
                mma16816h(o[2 * dbp + 1], phi[kk], &vh4[2]);
            }
        }
        __syncthreads();
    }

    // ---- epilogue: fp16 attn output ----
#pragma unroll
    for (int hh = 0; hh < 2; ++hh) {
        const float inv = 1.0f / l[hh];
        const int row = row0 + hh * 8;
        const size_t rb = ((size_t)(b * SLEN) + row) * (NH * HD) + h * HD;
#pragma unroll
        for (int db = 0; db < 8; ++db) {
            *(u32*)(g_Oh + rb + db * 8 + q2) =
                pack2h(o[db][2 * hh] * inv, o[db][2 * hh + 1] * inv);
        }
    }
}

// ---------------- launch ----------------
extern "C" void kernel_launch(void* const* d_in, const int* in_sizes, int n_in,
                              void* d_out, int out_size) {
    const float* hs  = (const float*)d_in[0];
    const int*   pos = (const int*)d_in[1];
    const float* Wq  = (const float*)d_in[2];
    const float* bq  = (const float*)d_in[3];
    const float* Wk  = (const float*)d_in[4];
    const float* bk  = (const float*)d_in[5];
    const float* Wv  = (const float*)d_in[6];
    const float* bv  = (const float*)d_in[7];
    const float* Wo  = (const float*)d_in[8];
    float* out = (float*)d_out;

    (void)in_sizes; (void)n_in; (void)out_size;

    cudaFuncSetAttribute(tc_gemm<0>, cudaFuncAttributeMaxDynamicSharedMemorySize, G_SMEM);
    cudaFuncSetAttribute(tc_gemm<1>, cudaFuncAttributeMaxDynamicSharedMemorySize, G_SMEM);
    cudaFuncSetAttribute(flash_mma, cudaFuncAttributeMaxDynamicSharedMemorySize, F_SMEM);

    convert_kernel<<<(NA + NW) / 4 / 256, 256>>>(hs, Wq, Wk, Wv, Wo);

    // fused QKV projection: nb 0..6 Q, 7 K, 8 V
    tc_gemm<0><<<dim3(9, 64), 256, G_SMEM>>>(bq, bk, bv, nullptr);

    {
        const int qrows = BATCH * NH * SLEN;
        const int krows = BATCH * NKV * SLEN;
        const int total = (qrows + krows) * (HD / 2);
        rope_split_kernel<<<total / 256, 256>>>(pos);
    }

    flash_mma<<<dim3(SLEN / 128, NH, BATCH), 256, F_SMEM>>>();

    // O projection -> d_out
    tc_gemm<1><<<dim3(7, 64), 256, G_SMEM>>>(nullptr, nullptr, nullptr, out);
}